// round 1
// baseline (speedup 1.0000x reference)
#include <cuda_runtime.h>
#include <math_constants.h>

// Problem constants (fixed by the reference)
constexpr int Bb  = 2;
constexpr int Ss  = 2048;
constexpr int Dd  = 1024;
constexpr int Hh  = 16;
constexpr int DKk = 64;           // head dim
constexpr int MM  = Bb * Ss;      // 4096 rows

// Scratch (allocation-free rule: __device__ globals)
__device__ float g_q[Bb * Ss * Dd];
__device__ float g_k[Bb * Ss * Dd];
__device__ float g_v[Bb * Ss * Dd];
__device__ float g_o[Bb * Ss * Dd];

// ---------------------------------------------------------------------------
// GEMM: C[M,N] = A[M,K] * W[N,K]^T   (both operands K-contiguous, NT form)
// BM=BN=128, BK=8, 256 threads, 8x8 microtile per thread.
// ---------------------------------------------------------------------------
__global__ void __launch_bounds__(256)
gemm_nt(const float* __restrict__ A, const float* __restrict__ W,
        float* __restrict__ C, int M, int N, int K)
{
    constexpr int BM = 128, BN = 128, BK = 8;
    __shared__ float As[BK][BM + 4];
    __shared__ float Bs[BK][BN + 4];

    const int bm  = blockIdx.y * BM;
    const int bn  = blockIdx.x * BN;
    const int tid = threadIdx.x;
    const int tx  = tid & 15;      // 0..15 (cols)
    const int ty  = tid >> 4;      // 0..15 (rows)

    // Loader mapping: each thread loads one float4 from A and one from W per k-step
    const int lrow = tid >> 1;             // 0..127
    const int lcol = (tid & 1) * 4;        // 0 or 4
    const float* Ap = A + (size_t)(bm + lrow) * K + lcol;
    const float* Wp = W + (size_t)(bn + lrow) * K + lcol;

    float acc[8][8] = {};

    for (int k0 = 0; k0 < K; k0 += BK) {
        float4 a4 = *(const float4*)(Ap + k0);
        float4 b4 = *(const float4*)(Wp + k0);
        As[lcol + 0][lrow] = a4.x; As[lcol + 1][lrow] = a4.y;
        As[lcol + 2][lrow] = a4.z; As[lcol + 3][lrow] = a4.w;
        Bs[lcol + 0][lrow] = b4.x; Bs[lcol + 1][lrow] = b4.y;
        Bs[lcol + 2][lrow] = b4.z; Bs[lcol + 3][lrow] = b4.w;
        __syncthreads();

        #pragma unroll
        for (int kk = 0; kk < BK; kk++) {
            float4 a0 = *(const float4*)&As[kk][ty * 8];
            float4 a1 = *(const float4*)&As[kk][ty * 8 + 4];
            float4 b0 = *(const float4*)&Bs[kk][tx * 8];
            float4 b1 = *(const float4*)&Bs[kk][tx * 8 + 4];
            float af[8] = {a0.x, a0.y, a0.z, a0.w, a1.x, a1.y, a1.z, a1.w};
            float bf[8] = {b0.x, b0.y, b0.z, b0.w, b1.x, b1.y, b1.z, b1.w};
            #pragma unroll
            for (int i = 0; i < 8; i++)
                #pragma unroll
                for (int j = 0; j < 8; j++)
                    acc[i][j] += af[i] * bf[j];
        }
        __syncthreads();
    }

    #pragma unroll
    for (int i = 0; i < 8; i++) {
        float* crow = C + (size_t)(bm + ty * 8 + i) * N + bn + tx * 8;
        float4 c0 = {acc[i][0], acc[i][1], acc[i][2], acc[i][3]};
        float4 c1 = {acc[i][4], acc[i][5], acc[i][6], acc[i][7]};
        *(float4*)(crow)     = c0;
        *(float4*)(crow + 4) = c1;
    }
}

// ---------------------------------------------------------------------------
// RoPE applied in-place to Q and K (layout [B*S, D], head-major within row).
// One thread per (row, head, pair). Matches ref: ang = float(pos) * float(freq).
// ---------------------------------------------------------------------------
__global__ void rope_kernel(float* __restrict__ Q, float* __restrict__ K,
                            const int* __restrict__ pos)
{
    const int total = Bb * Ss * Hh * (DKk / 2);
    int idx = blockIdx.x * blockDim.x + threadIdx.x;
    if (idx >= total) return;

    const int j    = idx & 31;            // pair index 0..31
    const int rest = idx >> 5;            // (b*S+s)*H + h
    const int h    = rest & (Hh - 1);
    const int row  = rest >> 4;           // b*S + s
    const int s    = row & (Ss - 1);

    const float p    = (float)pos[s];
    // freq computed in double then rounded, to track the fp32 reference closely
    const float freq = (float)(pow(10000.0, -(double)(2 * j) / 64.0));
    const float ang  = p * freq;
    float sn, cs;
    sincosf(ang, &sn, &cs);

    const int base = row * Dd + h * DKk + 2 * j;

    float q0 = Q[base], q1 = Q[base + 1];
    Q[base]     = cs * q0 - sn * q1;
    Q[base + 1] = sn * q0 + cs * q1;

    float k0 = K[base], k1 = K[base + 1];
    K[base]     = cs * k0 - sn * k1;
    K[base + 1] = sn * k0 + cs * k1;
}

// ---------------------------------------------------------------------------
// Causal flash attention. Thread-per-query, 128 queries/block, 64-key smem
// tiles, online softmax merged in chunks of 16 keys.
// Q/K/V are [B*S, D] with head h occupying columns [h*64, h*64+64).
// ---------------------------------------------------------------------------
__global__ void __launch_bounds__(128)
fa_kernel(const float* __restrict__ Q, const float* __restrict__ K,
          const float* __restrict__ V, float* __restrict__ O)
{
    constexpr int BMq = 128, BNk = 64, CH = 16;
    __shared__ float Ks[BNk][DKk];
    __shared__ float Vs[BNk][DKk];

    const int bh = blockIdx.y;
    const int b  = bh >> 4;
    const int h  = bh & (Hh - 1);
    const int q0 = blockIdx.x * BMq;
    const int tid = threadIdx.x;
    const int sq  = q0 + tid;                 // this thread's query position

    const float* qp = Q + (size_t)(b * Ss + sq) * Dd + h * DKk;
    float4 q4[16];
    #pragma unroll
    for (int i = 0; i < 16; i++) q4[i] = *(const float4*)(qp + 4 * i);

    float o[DKk] = {};
    float m = -CUDART_INF_F;
    float l = 0.f;

    const float* kbase = K + (size_t)(b * Ss) * Dd + h * DKk;
    const float* vbase = V + (size_t)(b * Ss) * Dd + h * DKk;

    const int ntiles = (q0 + BMq) / BNk;      // tiles needed to cover q0+127

    for (int t = 0; t < ntiles; t++) {
        const int k0 = t * BNk;
        __syncthreads();   // protect previous tile's smem from overwrite
        for (int i = tid; i < BNk * DKk / 4; i += BMq) {
            const int r = i >> 4;             // 16 float4 per row
            const int c = (i & 15) * 4;
            *(float4*)&Ks[r][c] = *(const float4*)(kbase + (size_t)(k0 + r) * Dd + c);
            *(float4*)&Vs[r][c] = *(const float4*)(vbase + (size_t)(k0 + r) * Dd + c);
        }
        __syncthreads();

        const int lim = sq - k0;              // max allowed local key index

        for (int c0 = 0; c0 < BNk && c0 <= lim; c0 += CH) {
            float sc[CH];
            float cmax = -CUDART_INF_F;
            #pragma unroll
            for (int jj = 0; jj < CH; jj++) {
                const int j = c0 + jj;
                const float4* kr = (const float4*)Ks[j];
                float d0 = 0.f, d1 = 0.f, d2 = 0.f, d3 = 0.f;
                #pragma unroll
                for (int dd = 0; dd < 16; dd++) {
                    float4 kv = kr[dd];
                    d0 += q4[dd].x * kv.x;
                    d1 += q4[dd].y * kv.y;
                    d2 += q4[dd].z * kv.z;
                    d3 += q4[dd].w * kv.w;
                }
                float dot = ((d0 + d1) + (d2 + d3)) * 0.125f;  // 1/sqrt(64)
                if (j > lim) dot = -CUDART_INF_F;
                sc[jj] = dot;
                cmax = fmaxf(cmax, dot);
            }
            // chunk guaranteed non-empty: j=c0 <= lim, so cmax is finite
            const float mnew = fmaxf(m, cmax);
            const float corr = __expf(m - mnew);   // first chunk: exp(-inf)=0
            l *= corr;
            #pragma unroll
            for (int dd = 0; dd < DKk; dd++) o[dd] *= corr;

            #pragma unroll
            for (int jj = 0; jj < CH; jj++) {
                const float pw = __expf(sc[jj] - mnew);   // masked -> 0
                l += pw;
                const float4* vr = (const float4*)Vs[c0 + jj];
                #pragma unroll
                for (int dd = 0; dd < 16; dd++) {
                    float4 vv = vr[dd];
                    o[4 * dd + 0] += pw * vv.x;
                    o[4 * dd + 1] += pw * vv.y;
                    o[4 * dd + 2] += pw * vv.z;
                    o[4 * dd + 3] += pw * vv.w;
                }
            }
            m = mnew;
        }
    }

    const float inv = 1.f / l;                 // diagonal always present: l >= exp(0-m) > 0
    float* op = O + (size_t)(b * Ss + sq) * Dd + h * DKk;
    #pragma unroll
    for (int dd = 0; dd < 16; dd++) {
        float4 r;
        r.x = o[4 * dd + 0] * inv;
        r.y = o[4 * dd + 1] * inv;
        r.z = o[4 * dd + 2] * inv;
        r.w = o[4 * dd + 3] * inv;
        *(float4*)(op + 4 * dd) = r;
    }
}

// ---------------------------------------------------------------------------
// Launch
// ---------------------------------------------------------------------------
extern "C" void kernel_launch(void* const* d_in, const int* in_sizes, int n_in,
                              void* d_out, int out_size)
{
    const float* x   = (const float*)d_in[0];
    const int*   pos = (const int*)  d_in[1];
    const float* WQ  = (const float*)d_in[2];
    const float* WK  = (const float*)d_in[3];
    const float* WV  = (const float*)d_in[4];
    const float* WO  = (const float*)d_in[5];
    float* out = (float*)d_out;

    float *qp, *kp, *vp, *op;
    cudaGetSymbolAddress((void**)&qp, g_q);
    cudaGetSymbolAddress((void**)&kp, g_k);
    cudaGetSymbolAddress((void**)&vp, g_v);
    cudaGetSymbolAddress((void**)&op, g_o);

    dim3 ggrid(Dd / 128, MM / 128);   // (8, 32)

    // Projections
    gemm_nt<<<ggrid, 256>>>(x, WQ, qp, MM, Dd, Dd);
    gemm_nt<<<ggrid, 256>>>(x, WK, kp, MM, Dd, Dd);
    gemm_nt<<<ggrid, 256>>>(x, WV, vp, MM, Dd, Dd);

    // RoPE on Q, K
    {
        const int total = Bb * Ss * Hh * (DKk / 2);
        rope_kernel<<<(total + 255) / 256, 256>>>(qp, kp, pos);
    }

    // Causal flash attention
    {
        dim3 fgrid(Ss / 128, Bb * Hh);   // (16, 32)
        fa_kernel<<<fgrid, 128>>>(qp, kp, vp, op);
    }

    // Output projection
    gemm_nt<<<ggrid, 256>>>(op, WO, out, MM, Dd, Dd);
}

// round 2
// speedup vs baseline: 1.1439x; 1.1439x over previous
#include <cuda_runtime.h>
#include <math_constants.h>

// Problem constants (fixed by the reference)
constexpr int Bb  = 2;
constexpr int Ss  = 2048;
constexpr int Dd  = 1024;
constexpr int Hh  = 16;
constexpr int DKk = 64;           // head dim
constexpr int MM  = Bb * Ss;      // 4096 rows

// Scratch (allocation-free rule: __device__ globals)
__device__ float g_q[Bb * Ss * Dd];
__device__ float g_k[Bb * Ss * Dd];
__device__ float g_v[Bb * Ss * Dd];
__device__ float g_o[Bb * Ss * Dd];

// ---------------------------------------------------------------------------
// GEMM: C[M,N] = A[M,K] * W[N,K]^T   (both operands K-contiguous, NT form)
// BM=BN=128, BK=8, 256 threads, 8x8 microtile per thread.
// Fused 3-way variant: blockIdx.z selects among {WQ->g_q, WK->g_k, WV->g_v}.
// ---------------------------------------------------------------------------
__device__ __forceinline__ void gemm_nt_body(
    const float* __restrict__ A, const float* __restrict__ W,
    float* __restrict__ C, int M, int N, int K)
{
    constexpr int BM = 128, BN = 128, BK = 8;
    __shared__ float As[BK][BM + 4];
    __shared__ float Bs[BK][BN + 4];

    const int bm  = blockIdx.y * BM;
    const int bn  = blockIdx.x * BN;
    const int tid = threadIdx.x;
    const int tx  = tid & 15;      // 0..15 (cols)
    const int ty  = tid >> 4;      // 0..15 (rows)

    const int lrow = tid >> 1;             // 0..127
    const int lcol = (tid & 1) * 4;        // 0 or 4
    const float* Ap = A + (size_t)(bm + lrow) * K + lcol;
    const float* Wp = W + (size_t)(bn + lrow) * K + lcol;

    float acc[8][8] = {};

    for (int k0 = 0; k0 < K; k0 += BK) {
        float4 a4 = *(const float4*)(Ap + k0);
        float4 b4 = *(const float4*)(Wp + k0);
        As[lcol + 0][lrow] = a4.x; As[lcol + 1][lrow] = a4.y;
        As[lcol + 2][lrow] = a4.z; As[lcol + 3][lrow] = a4.w;
        Bs[lcol + 0][lrow] = b4.x; Bs[lcol + 1][lrow] = b4.y;
        Bs[lcol + 2][lrow] = b4.z; Bs[lcol + 3][lrow] = b4.w;
        __syncthreads();

        #pragma unroll
        for (int kk = 0; kk < BK; kk++) {
            float4 a0 = *(const float4*)&As[kk][ty * 8];
            float4 a1 = *(const float4*)&As[kk][ty * 8 + 4];
            float4 b0 = *(const float4*)&Bs[kk][tx * 8];
            float4 b1 = *(const float4*)&Bs[kk][tx * 8 + 4];
            float af[8] = {a0.x, a0.y, a0.z, a0.w, a1.x, a1.y, a1.z, a1.w};
            float bf[8] = {b0.x, b0.y, b0.z, b0.w, b1.x, b1.y, b1.z, b1.w};
            #pragma unroll
            for (int i = 0; i < 8; i++)
                #pragma unroll
                for (int j = 0; j < 8; j++)
                    acc[i][j] += af[i] * bf[j];
        }
        __syncthreads();
    }

    #pragma unroll
    for (int i = 0; i < 8; i++) {
        float* crow = C + (size_t)(bm + ty * 8 + i) * N + bn + tx * 8;
        float4 c0 = {acc[i][0], acc[i][1], acc[i][2], acc[i][3]};
        float4 c1 = {acc[i][4], acc[i][5], acc[i][6], acc[i][7]};
        *(float4*)(crow)     = c0;
        *(float4*)(crow + 4) = c1;
    }
}

__global__ void __launch_bounds__(256)
gemm_nt(const float* __restrict__ A, const float* __restrict__ W,
        float* __restrict__ C, int M, int N, int K)
{
    gemm_nt_body(A, W, C, M, N, K);
}

// Fused Q/K/V projection: z dimension picks the weight and destination.
__global__ void __launch_bounds__(256)
gemm_qkv(const float* __restrict__ A,
         const float* __restrict__ WQ, const float* __restrict__ WK,
         const float* __restrict__ WV,
         float* __restrict__ Cq, float* __restrict__ Ck, float* __restrict__ Cv,
         int M, int N, int K)
{
    const float* W = (blockIdx.z == 0) ? WQ : (blockIdx.z == 1) ? WK : WV;
    float*       C = (blockIdx.z == 0) ? Cq : (blockIdx.z == 1) ? Ck : Cv;
    gemm_nt_body(A, W, C, M, N, K);
}

// ---------------------------------------------------------------------------
// RoPE applied in-place to Q and K. All fp32 (no FP64 pipe!).
// freq = 10000^(-2j/64) = exp2f(-(2j/64) * log2(10000))
// ---------------------------------------------------------------------------
__global__ void rope_kernel(float* __restrict__ Q, float* __restrict__ K,
                            const int* __restrict__ pos)
{
    const int total = Bb * Ss * Hh * (DKk / 2);
    int idx = blockIdx.x * blockDim.x + threadIdx.x;
    if (idx >= total) return;

    const int j    = idx & 31;            // pair index 0..31
    const int rest = idx >> 5;            // (b*S+s)*H + h
    const int h    = rest & (Hh - 1);
    const int row  = rest >> 4;           // b*S + s
    const int s    = row & (Ss - 1);

    const float p = (float)pos[s];
    // log2(10000) = 13.2877123795494...
    const float freq = exp2f((float)j * (-2.0f / 64.0f) * 13.28771237954945f);
    const float ang  = p * freq;
    float sn, cs;
    sincosf(ang, &sn, &cs);

    const int base = row * Dd + h * DKk + 2 * j;

    float2 q = *(float2*)&Q[base];
    float2 k = *(float2*)&K[base];
    float2 qo = {cs * q.x - sn * q.y, sn * q.x + cs * q.y};
    float2 ko = {cs * k.x - sn * k.y, sn * k.x + cs * k.y};
    *(float2*)&Q[base] = qo;
    *(float2*)&K[base] = ko;
}

// ---------------------------------------------------------------------------
// Causal flash attention. Thread-per-query, 128 queries/block, 64-key smem
// tiles, online softmax merged in chunks of 16 keys.
// ---------------------------------------------------------------------------
__global__ void __launch_bounds__(128)
fa_kernel(const float* __restrict__ Q, const float* __restrict__ K,
          const float* __restrict__ V, float* __restrict__ O)
{
    constexpr int BMq = 128, BNk = 64, CH = 16;
    __shared__ float Ks[BNk][DKk];
    __shared__ float Vs[BNk][DKk];

    const int bh = blockIdx.y;
    const int b  = bh >> 4;
    const int h  = bh & (Hh - 1);
    const int q0 = blockIdx.x * BMq;
    const int tid = threadIdx.x;
    const int sq  = q0 + tid;                 // this thread's query position

    const float* qp = Q + (size_t)(b * Ss + sq) * Dd + h * DKk;
    float4 q4[16];
    #pragma unroll
    for (int i = 0; i < 16; i++) q4[i] = *(const float4*)(qp + 4 * i);

    float o[DKk] = {};
    float m = -CUDART_INF_F;
    float l = 0.f;

    const float* kbase = K + (size_t)(b * Ss) * Dd + h * DKk;
    const float* vbase = V + (size_t)(b * Ss) * Dd + h * DKk;

    const int ntiles = (q0 + BMq) / BNk;

    for (int t = 0; t < ntiles; t++) {
        const int k0 = t * BNk;
        __syncthreads();
        for (int i = tid; i < BNk * DKk / 4; i += BMq) {
            const int r = i >> 4;
            const int c = (i & 15) * 4;
            *(float4*)&Ks[r][c] = *(const float4*)(kbase + (size_t)(k0 + r) * Dd + c);
            *(float4*)&Vs[r][c] = *(const float4*)(vbase + (size_t)(k0 + r) * Dd + c);
        }
        __syncthreads();

        const int lim = sq - k0;

        for (int c0 = 0; c0 < BNk && c0 <= lim; c0 += CH) {
            float sc[CH];
            float cmax = -CUDART_INF_F;
            #pragma unroll
            for (int jj = 0; jj < CH; jj++) {
                const int j = c0 + jj;
                const float4* kr = (const float4*)Ks[j];
                float d0 = 0.f, d1 = 0.f, d2 = 0.f, d3 = 0.f;
                #pragma unroll
                for (int dd = 0; dd < 16; dd++) {
                    float4 kv = kr[dd];
                    d0 += q4[dd].x * kv.x;
                    d1 += q4[dd].y * kv.y;
                    d2 += q4[dd].z * kv.z;
                    d3 += q4[dd].w * kv.w;
                }
                float dot = ((d0 + d1) + (d2 + d3)) * 0.125f;
                if (j > lim) dot = -CUDART_INF_F;
                sc[jj] = dot;
                cmax = fmaxf(cmax, dot);
            }
            const float mnew = fmaxf(m, cmax);
            const float corr = __expf(m - mnew);
            l *= corr;
            #pragma unroll
            for (int dd = 0; dd < DKk; dd++) o[dd] *= corr;

            #pragma unroll
            for (int jj = 0; jj < CH; jj++) {
                const float pw = __expf(sc[jj] - mnew);
                l += pw;
                const float4* vr = (const float4*)Vs[c0 + jj];
                #pragma unroll
                for (int dd = 0; dd < 16; dd++) {
                    float4 vv = vr[dd];
                    o[4 * dd + 0] += pw * vv.x;
                    o[4 * dd + 1] += pw * vv.y;
                    o[4 * dd + 2] += pw * vv.z;
                    o[4 * dd + 3] += pw * vv.w;
                }
            }
            m = mnew;
        }
    }

    const float inv = 1.f / l;
    float* op = O + (size_t)(b * Ss + sq) * Dd + h * DKk;
    #pragma unroll
    for (int dd = 0; dd < 16; dd++) {
        float4 r;
        r.x = o[4 * dd + 0] * inv;
        r.y = o[4 * dd + 1] * inv;
        r.z = o[4 * dd + 2] * inv;
        r.w = o[4 * dd + 3] * inv;
        *(float4*)(op + 4 * dd) = r;
    }
}

// ---------------------------------------------------------------------------
// Launch
// ---------------------------------------------------------------------------
extern "C" void kernel_launch(void* const* d_in, const int* in_sizes, int n_in,
                              void* d_out, int out_size)
{
    const float* x   = (const float*)d_in[0];
    const int*   pos = (const int*)  d_in[1];
    const float* WQ  = (const float*)d_in[2];
    const float* WK  = (const float*)d_in[3];
    const float* WV  = (const float*)d_in[4];
    const float* WO  = (const float*)d_in[5];
    float* out = (float*)d_out;

    float *qp, *kp, *vp, *op;
    cudaGetSymbolAddress((void**)&qp, g_q);
    cudaGetSymbolAddress((void**)&kp, g_k);
    cudaGetSymbolAddress((void**)&vp, g_v);
    cudaGetSymbolAddress((void**)&op, g_o);

    // Fused Q/K/V projections: one launch, grid.z = 3
    {
        dim3 grid(Dd / 128, MM / 128, 3);   // (8, 32, 3) = 768 blocks
        gemm_qkv<<<grid, 256>>>(x, WQ, WK, WV, qp, kp, vp, MM, Dd, Dd);
    }

    // RoPE on Q, K (fp32-only transcendentals)
    {
        const int total = Bb * Ss * Hh * (DKk / 2);
        rope_kernel<<<(total + 255) / 256, 256>>>(qp, kp, pos);
    }

    // Causal flash attention
    {
        dim3 fgrid(Ss / 128, Bb * Hh);   // (16, 32)
        fa_kernel<<<fgrid, 128>>>(qp, kp, vp, op);
    }

    // Output projection
    {
        dim3 ggrid(Dd / 128, MM / 128);  // (8, 32)
        gemm_nt<<<ggrid, 256>>>(op, WO, out, MM, Dd, Dd);
    }
}

// round 4
// speedup vs baseline: 1.5975x; 1.3965x over previous
#include <cuda_runtime.h>
#include <cuda_bf16.h>
#include <math_constants.h>
#include <cstdint>

// Problem constants
constexpr int Bb  = 2;
constexpr int Ss  = 2048;
constexpr int Dd  = 1024;
constexpr int Hh  = 16;
constexpr int DKk = 64;
constexpr int MM  = Bb * Ss;      // 4096

// fp32 scratch
__device__ float g_q[MM * Dd];
__device__ float g_k[MM * Dd];
__device__ float g_v[MM * Dd];
__device__ float g_o[MM * Dd];
// bf16 hi/lo scratch
__device__ __nv_bfloat16 g_xhi[MM * Dd];
__device__ __nv_bfloat16 g_xlo[MM * Dd];
__device__ __nv_bfloat16 g_whi[4 * Dd * Dd];   // Q,K,V,O order
__device__ __nv_bfloat16 g_wlo[4 * Dd * Dd];
__device__ __nv_bfloat16 g_ohi[MM * Dd];
__device__ __nv_bfloat16 g_olo[MM * Dd];

// ---------------------------------------------------------------------------
// Warp-level MMA helpers (sm_80+ instructions; no tcgen05 — ptxas targets sm_103)
// ---------------------------------------------------------------------------
__device__ __forceinline__ uint32_t smem_u32(const void* p) {
    uint32_t a;
    asm("{ .reg .u64 t; cvta.to.shared.u64 t, %1; cvt.u32.u64 %0, t; }"
        : "=r"(a) : "l"(p));
    return a;
}

__device__ __forceinline__ void mma16816(float* c, const uint32_t* a, const uint32_t* b) {
    asm volatile(
        "mma.sync.aligned.m16n8k16.row.col.f32.bf16.bf16.f32 "
        "{%0,%1,%2,%3}, {%4,%5,%6,%7}, {%8,%9}, {%0,%1,%2,%3};"
        : "+f"(c[0]), "+f"(c[1]), "+f"(c[2]), "+f"(c[3])
        : "r"(a[0]), "r"(a[1]), "r"(a[2]), "r"(a[3]), "r"(b[0]), "r"(b[1]));
}

__device__ __forceinline__ void ldsm4(uint32_t* r, uint32_t a) {
    asm volatile("ldmatrix.sync.aligned.m8n8.x4.shared.b16 {%0,%1,%2,%3}, [%4];"
        : "=r"(r[0]), "=r"(r[1]), "=r"(r[2]), "=r"(r[3]) : "r"(a));
}

__device__ __forceinline__ void cp_async16(uint32_t dst, const void* src) {
    asm volatile("cp.async.cg.shared.global [%0], [%1], 16;" :: "r"(dst), "l"(src) : "memory");
}
__device__ __forceinline__ void cp_commit() {
    asm volatile("cp.async.commit_group;" ::: "memory");
}
__device__ __forceinline__ void cp_wait1() {
    asm volatile("cp.async.wait_group 1;" ::: "memory");
}
__device__ __forceinline__ void cp_wait0() {
    asm volatile("cp.async.wait_group 0;" ::: "memory");
}

// ---------------------------------------------------------------------------
// Split-bf16 HMMA GEMM: C[M,N] = A[M,K]*B[N,K]^T, fp32-equivalent via
// Ahi*Bhi + Ahi*Blo + Alo*Bhi (fp32 accum). 128x128 tile/CTA, BK=32,
// 8 warps (64x32 warp tile), cp.async double buffer.
// ---------------------------------------------------------------------------
constexpr int LDA    = 40;                    // padded bf16 row (80 bytes)
constexpr int MAT_SZ = 128 * LDA * 2;         // 10240 B per matrix
constexpr int STG_SZ = 4 * MAT_SZ;            // Ahi,Alo,Bhi,Blo per stage: 40960 B
constexpr int MG_SMEM = 2 * STG_SZ;           // 81920 B

__device__ __forceinline__ void mma_gemm_body(
    const __nv_bfloat16* __restrict__ Ahi, const __nv_bfloat16* __restrict__ Alo,
    const __nv_bfloat16* __restrict__ Bhi, const __nv_bfloat16* __restrict__ Blo,
    float* __restrict__ C, int N, int K)
{
    extern __shared__ char smem[];
    const uint32_t sb = smem_u32(smem);

    const int tid = threadIdx.x;
    const int wid = tid >> 5;
    const int lid = tid & 31;
    const int bm  = blockIdx.y * 128;
    const int bn  = blockIdx.x * 128;
    const int wm  = wid >> 2;          // 0..1 -> rows wm*64
    const int wn  = wid & 3;           // 0..3 -> cols wn*32

    const int nIter = K / 32;

    // --- async loader: stage s <- K-chunk c (32 cols) ---
    auto load_chunk = [&](int c, int s) {
        const int koff = c * 32;
        const uint32_t st = sb + s * STG_SZ;
        #pragma unroll
        for (int i = tid; i < 512; i += 256) {
            const int r = i >> 2;                  // 0..127
            const int q = (i & 3) * 8;             // element offset within chunk
            const uint32_t d = (uint32_t)(r * 80 + q * 2);
            const size_t ga = (size_t)(bm + r) * K + koff + q;
            const size_t gb = (size_t)(bn + r) * K + koff + q;
            cp_async16(st +              d, Ahi + ga);
            cp_async16(st + MAT_SZ     + d, Alo + ga);
            cp_async16(st + 2 * MAT_SZ + d, Bhi + gb);
            cp_async16(st + 3 * MAT_SZ + d, Blo + gb);
        }
        cp_commit();
    };

    float acc[4][4][4] = {};

    load_chunk(0, 0);
    load_chunk(1, 1);

    // ldmatrix lane addressing
    const int ri = lid & 7;
    const int g  = lid >> 3;           // 0..3
    const int ag_r = ((g & 1) << 3) + ri;      // A: row offset within 16
    const int ag_c = (g >> 1) << 3;            // A: col offset (0 or 8)
    const int bg_r = ((g >> 1) << 3) + ri;     // B: row offset within 16
    const int bg_c = (g & 1) << 3;             // B: col offset (0 or 8)

    for (int c = 0; c < nIter; c++) {
        if (c + 2 < nIter) cp_wait1(); else cp_wait0();
        __syncthreads();

        const uint32_t st  = sb + (uint32_t)(c & 1) * STG_SZ;
        const uint32_t sAh = st;
        const uint32_t sAl = st + MAT_SZ;
        const uint32_t sBh = st + 2 * MAT_SZ;
        const uint32_t sBl = st + 3 * MAT_SZ;

        #pragma unroll
        for (int k16 = 0; k16 < 32; k16 += 16) {
            uint32_t ah[4][4], al[4][4], bh[2][4], bl[2][4];
            #pragma unroll
            for (int mt = 0; mt < 4; mt++) {
                const uint32_t off = (uint32_t)((wm * 64 + mt * 16 + ag_r) * 80
                                                + (k16 + ag_c) * 2);
                ldsm4(ah[mt], sAh + off);
                ldsm4(al[mt], sAl + off);
            }
            #pragma unroll
            for (int np = 0; np < 2; np++) {
                const uint32_t off = (uint32_t)((wn * 32 + np * 16 + bg_r) * 80
                                                + (k16 + bg_c) * 2);
                ldsm4(bh[np], sBh + off);
                ldsm4(bl[np], sBl + off);
            }
            #pragma unroll
            for (int mt = 0; mt < 4; mt++) {
                #pragma unroll
                for (int nt = 0; nt < 4; nt++) {
                    const uint32_t* bhp = &bh[nt >> 1][(nt & 1) * 2];
                    const uint32_t* blp = &bl[nt >> 1][(nt & 1) * 2];
                    mma16816(acc[mt][nt], ah[mt], bhp);
                    mma16816(acc[mt][nt], ah[mt], blp);
                    mma16816(acc[mt][nt], al[mt], bhp);
                }
            }
        }
        __syncthreads();
        if (c + 2 < nIter) load_chunk(c + 2, c & 1);
    }

    // Epilogue: fragment -> gmem (float2 per quad)
    const int cr = lid >> 2;           // 0..7
    const int cc = (lid & 3) * 2;      // 0,2,4,6
    #pragma unroll
    for (int mt = 0; mt < 4; mt++) {
        #pragma unroll
        for (int nt = 0; nt < 4; nt++) {
            const int row = bm + wm * 64 + mt * 16 + cr;
            const int col = bn + wn * 32 + nt * 8 + cc;
            float2 v0 = {acc[mt][nt][0], acc[mt][nt][1]};
            float2 v1 = {acc[mt][nt][2], acc[mt][nt][3]};
            *(float2*)&C[(size_t)row * N + col]       = v0;
            *(float2*)&C[(size_t)(row + 8) * N + col] = v1;
        }
    }
}

__global__ void __launch_bounds__(256)
mma_gemm(const __nv_bfloat16* __restrict__ Ahi, const __nv_bfloat16* __restrict__ Alo,
         const __nv_bfloat16* __restrict__ Bhi, const __nv_bfloat16* __restrict__ Blo,
         float* __restrict__ C, int N, int K)
{
    mma_gemm_body(Ahi, Alo, Bhi, Blo, C, N, K);
}

__global__ void __launch_bounds__(256)
mma_gemm_qkv(const __nv_bfloat16* __restrict__ xhi, const __nv_bfloat16* __restrict__ xlo,
             const __nv_bfloat16* __restrict__ whi, const __nv_bfloat16* __restrict__ wlo,
             float* __restrict__ Cq, float* __restrict__ Ck, float* __restrict__ Cv)
{
    const int z = blockIdx.z;
    const __nv_bfloat16* Bh = whi + (size_t)z * Dd * Dd;
    const __nv_bfloat16* Bl = wlo + (size_t)z * Dd * Dd;
    float* C = (z == 0) ? Cq : (z == 1) ? Ck : Cv;
    mma_gemm_body(xhi, xlo, Bh, Bl, C, Dd, Dd);
}

// ---------------------------------------------------------------------------
// fp32 -> bf16 hi/lo split
// ---------------------------------------------------------------------------
__global__ void split_f32(const float* __restrict__ src,
                          __nv_bfloat16* __restrict__ hi,
                          __nv_bfloat16* __restrict__ lo, int n4)
{
    int i = blockIdx.x * blockDim.x + threadIdx.x;
    if (i >= n4) return;
    float4 x = ((const float4*)src)[i];
    __nv_bfloat16 h0 = __float2bfloat16(x.x);
    __nv_bfloat16 h1 = __float2bfloat16(x.y);
    __nv_bfloat16 h2 = __float2bfloat16(x.z);
    __nv_bfloat16 h3 = __float2bfloat16(x.w);
    __nv_bfloat16 l0 = __float2bfloat16(x.x - __bfloat162float(h0));
    __nv_bfloat16 l1 = __float2bfloat16(x.y - __bfloat162float(h1));
    __nv_bfloat16 l2 = __float2bfloat16(x.z - __bfloat162float(h2));
    __nv_bfloat16 l3 = __float2bfloat16(x.w - __bfloat162float(h3));
    ((__nv_bfloat162*)hi)[2 * i]     = __nv_bfloat162(h0, h1);
    ((__nv_bfloat162*)hi)[2 * i + 1] = __nv_bfloat162(h2, h3);
    ((__nv_bfloat162*)lo)[2 * i]     = __nv_bfloat162(l0, l1);
    ((__nv_bfloat162*)lo)[2 * i + 1] = __nv_bfloat162(l2, l3);
}

// ---------------------------------------------------------------------------
// RoPE (fp32 transcendentals only)
// ---------------------------------------------------------------------------
__global__ void rope_kernel(float* __restrict__ Q, float* __restrict__ K,
                            const int* __restrict__ pos)
{
    const int total = MM * Hh * (DKk / 2);
    int idx = blockIdx.x * blockDim.x + threadIdx.x;
    if (idx >= total) return;

    const int j    = idx & 31;
    const int rest = idx >> 5;
    const int h    = rest & (Hh - 1);
    const int row  = rest >> 4;
    const int s    = row & (Ss - 1);

    const float p    = (float)pos[s];
    const float freq = exp2f((float)j * (-2.0f / 64.0f) * 13.28771237954945f);
    float sn, cs;
    sincosf(p * freq, &sn, &cs);

    const int base = row * Dd + h * DKk + 2 * j;
    float2 q = *(float2*)&Q[base];
    float2 k = *(float2*)&K[base];
    float2 qo = {cs * q.x - sn * q.y, sn * q.x + cs * q.y};
    float2 ko = {cs * k.x - sn * k.y, sn * k.x + cs * k.y};
    *(float2*)&Q[base] = qo;
    *(float2*)&K[base] = ko;
}

// ---------------------------------------------------------------------------
// Causal flash attention (fp32 SIMT; unchanged)
// ---------------------------------------------------------------------------
__global__ void __launch_bounds__(128)
fa_kernel(const float* __restrict__ Q, const float* __restrict__ K,
          const float* __restrict__ V, float* __restrict__ O)
{
    constexpr int BMq = 128, BNk = 64, CH = 16;
    __shared__ float Ks[BNk][DKk];
    __shared__ float Vs[BNk][DKk];

    const int bh = blockIdx.y;
    const int b  = bh >> 4;
    const int h  = bh & (Hh - 1);
    const int q0 = blockIdx.x * BMq;
    const int tid = threadIdx.x;
    const int sq  = q0 + tid;

    const float* qp = Q + (size_t)(b * Ss + sq) * Dd + h * DKk;
    float4 q4[16];
    #pragma unroll
    for (int i = 0; i < 16; i++) q4[i] = *(const float4*)(qp + 4 * i);

    float o[DKk] = {};
    float m = -CUDART_INF_F;
    float l = 0.f;

    const float* kbase = K + (size_t)(b * Ss) * Dd + h * DKk;
    const float* vbase = V + (size_t)(b * Ss) * Dd + h * DKk;
    const int ntiles = (q0 + BMq) / BNk;

    for (int t = 0; t < ntiles; t++) {
        const int k0 = t * BNk;
        __syncthreads();
        for (int i = tid; i < BNk * DKk / 4; i += BMq) {
            const int r = i >> 4;
            const int c = (i & 15) * 4;
            *(float4*)&Ks[r][c] = *(const float4*)(kbase + (size_t)(k0 + r) * Dd + c);
            *(float4*)&Vs[r][c] = *(const float4*)(vbase + (size_t)(k0 + r) * Dd + c);
        }
        __syncthreads();

        const int lim = sq - k0;

        for (int c0 = 0; c0 < BNk && c0 <= lim; c0 += CH) {
            float sc[CH];
            float cmax = -CUDART_INF_F;
            #pragma unroll
            for (int jj = 0; jj < CH; jj++) {
                const int j = c0 + jj;
                const float4* kr = (const float4*)Ks[j];
                float d0 = 0.f, d1 = 0.f, d2 = 0.f, d3 = 0.f;
                #pragma unroll
                for (int dd = 0; dd < 16; dd++) {
                    float4 kv = kr[dd];
                    d0 += q4[dd].x * kv.x;
                    d1 += q4[dd].y * kv.y;
                    d2 += q4[dd].z * kv.z;
                    d3 += q4[dd].w * kv.w;
                }
                float dot = ((d0 + d1) + (d2 + d3)) * 0.125f;
                if (j > lim) dot = -CUDART_INF_F;
                sc[jj] = dot;
                cmax = fmaxf(cmax, dot);
            }
            const float mnew = fmaxf(m, cmax);
            const float corr = __expf(m - mnew);
            l *= corr;
            #pragma unroll
            for (int dd = 0; dd < DKk; dd++) o[dd] *= corr;

            #pragma unroll
            for (int jj = 0; jj < CH; jj++) {
                const float pw = __expf(sc[jj] - mnew);
                l += pw;
                const float4* vr = (const float4*)Vs[c0 + jj];
                #pragma unroll
                for (int dd = 0; dd < 16; dd++) {
                    float4 vv = vr[dd];
                    o[4 * dd + 0] += pw * vv.x;
                    o[4 * dd + 1] += pw * vv.y;
                    o[4 * dd + 2] += pw * vv.z;
                    o[4 * dd + 3] += pw * vv.w;
                }
            }
            m = mnew;
        }
    }

    const float inv = 1.f / l;
    float* op = O + (size_t)(b * Ss + sq) * Dd + h * DKk;
    #pragma unroll
    for (int dd = 0; dd < 16; dd++) {
        float4 r;
        r.x = o[4 * dd + 0] * inv;
        r.y = o[4 * dd + 1] * inv;
        r.z = o[4 * dd + 2] * inv;
        r.w = o[4 * dd + 3] * inv;
        *(float4*)(op + 4 * dd) = r;
    }
}

// ---------------------------------------------------------------------------
// Launch
// ---------------------------------------------------------------------------
extern "C" void kernel_launch(void* const* d_in, const int* in_sizes, int n_in,
                              void* d_out, int out_size)
{
    const float* x   = (const float*)d_in[0];
    const int*   pos = (const int*)  d_in[1];
    const float* W4[4] = { (const float*)d_in[2], (const float*)d_in[3],
                           (const float*)d_in[4], (const float*)d_in[5] };
    float* out = (float*)d_out;

    float *qp, *kp, *vp, *op;
    cudaGetSymbolAddress((void**)&qp, g_q);
    cudaGetSymbolAddress((void**)&kp, g_k);
    cudaGetSymbolAddress((void**)&vp, g_v);
    cudaGetSymbolAddress((void**)&op, g_o);
    __nv_bfloat16 *xhi, *xlo, *whi, *wlo, *ohi, *olo;
    cudaGetSymbolAddress((void**)&xhi, g_xhi);
    cudaGetSymbolAddress((void**)&xlo, g_xlo);
    cudaGetSymbolAddress((void**)&whi, g_whi);
    cudaGetSymbolAddress((void**)&wlo, g_wlo);
    cudaGetSymbolAddress((void**)&ohi, g_ohi);
    cudaGetSymbolAddress((void**)&olo, g_olo);

    cudaFuncSetAttribute(mma_gemm,     cudaFuncAttributeMaxDynamicSharedMemorySize, MG_SMEM);
    cudaFuncSetAttribute(mma_gemm_qkv, cudaFuncAttributeMaxDynamicSharedMemorySize, MG_SMEM);

    // Split x and weights to bf16 hi/lo
    split_f32<<<(MM * Dd / 4 + 255) / 256, 256>>>(x, xhi, xlo, MM * Dd / 4);
    for (int w = 0; w < 4; w++)
        split_f32<<<(Dd * Dd / 4 + 255) / 256, 256>>>(
            W4[w], whi + (size_t)w * Dd * Dd, wlo + (size_t)w * Dd * Dd, Dd * Dd / 4);

    // Q/K/V projections on tensor cores (one launch, z=3)
    {
        dim3 grid(Dd / 128, MM / 128, 3);
        mma_gemm_qkv<<<grid, 256, MG_SMEM>>>(xhi, xlo, whi, wlo, qp, kp, vp);
    }

    // RoPE
    {
        const int total = MM * Hh * (DKk / 2);
        rope_kernel<<<(total + 255) / 256, 256>>>(qp, kp, pos);
    }

    // Attention
    {
        dim3 fgrid(Ss / 128, Bb * Hh);
        fa_kernel<<<fgrid, 128>>>(qp, kp, vp, op);
    }

    // Output projection
    split_f32<<<(MM * Dd / 4 + 255) / 256, 256>>>(op, ohi, olo, MM * Dd / 4);
    {
        dim3 grid(Dd / 128, MM / 128);
        mma_gemm<<<grid, 256, MG_SMEM>>>(ohi, olo, whi + 3 * (size_t)Dd * Dd,
                                         wlo + 3 * (size_t)Dd * Dd, out, Dd, Dd);
    }
}

// round 8
// speedup vs baseline: 4.2246x; 2.6446x over previous
#include <cuda_runtime.h>
#include <cuda_bf16.h>
#include <math_constants.h>
#include <cstdint>

// Problem constants
constexpr int Bb  = 2;
constexpr int Ss  = 2048;
constexpr int Dd  = 1024;
constexpr int Hh  = 16;
constexpr int DKk = 64;
constexpr int MM  = Bb * Ss;      // 4096

// fp32 scratch (projection outputs)
__device__ float g_q[MM * Dd];
__device__ float g_k[MM * Dd];
__device__ float g_v[MM * Dd];
// bf16 hi/lo scratch
__device__ __nv_bfloat16 g_xhi[MM * Dd];
__device__ __nv_bfloat16 g_xlo[MM * Dd];
__device__ __nv_bfloat16 g_whi[4 * Dd * Dd];   // Q,K,V,O order
__device__ __nv_bfloat16 g_wlo[4 * Dd * Dd];
__device__ __nv_bfloat16 g_qhi[MM * Dd];
__device__ __nv_bfloat16 g_qlo[MM * Dd];
__device__ __nv_bfloat16 g_khi[MM * Dd];
__device__ __nv_bfloat16 g_klo[MM * Dd];
__device__ __nv_bfloat16 g_vhi[MM * Dd];
__device__ __nv_bfloat16 g_vlo[MM * Dd];
__device__ __nv_bfloat16 g_ohi[MM * Dd];
__device__ __nv_bfloat16 g_olo[MM * Dd];

// ---------------------------------------------------------------------------
// Warp-level MMA helpers (sm_80+ instructions)
// ---------------------------------------------------------------------------
__device__ __forceinline__ uint32_t smem_u32(const void* p) {
    uint32_t a;
    asm("{ .reg .u64 t; cvta.to.shared.u64 t, %1; cvt.u32.u64 %0, t; }"
        : "=r"(a) : "l"(p));
    return a;
}

__device__ __forceinline__ void mma16816(float* c, const uint32_t* a, const uint32_t* b) {
    asm volatile(
        "mma.sync.aligned.m16n8k16.row.col.f32.bf16.bf16.f32 "
        "{%0,%1,%2,%3}, {%4,%5,%6,%7}, {%8,%9}, {%0,%1,%2,%3};"
        : "+f"(c[0]), "+f"(c[1]), "+f"(c[2]), "+f"(c[3])
        : "r"(a[0]), "r"(a[1]), "r"(a[2]), "r"(a[3]), "r"(b[0]), "r"(b[1]));
}

__device__ __forceinline__ void ldsm4(uint32_t* r, uint32_t a) {
    asm volatile("ldmatrix.sync.aligned.m8n8.x4.shared.b16 {%0,%1,%2,%3}, [%4];"
        : "=r"(r[0]), "=r"(r[1]), "=r"(r[2]), "=r"(r[3]) : "r"(a));
}
__device__ __forceinline__ void ldsm4t(uint32_t* r, uint32_t a) {
    asm volatile("ldmatrix.sync.aligned.m8n8.x4.trans.shared.b16 {%0,%1,%2,%3}, [%4];"
        : "=r"(r[0]), "=r"(r[1]), "=r"(r[2]), "=r"(r[3]) : "r"(a));
}

__device__ __forceinline__ void cp_async16(uint32_t dst, const void* src) {
    asm volatile("cp.async.cg.shared.global [%0], [%1], 16;" :: "r"(dst), "l"(src) : "memory");
}
__device__ __forceinline__ void cp_commit() { asm volatile("cp.async.commit_group;" ::: "memory"); }
__device__ __forceinline__ void cp_wait1()  { asm volatile("cp.async.wait_group 1;" ::: "memory"); }
__device__ __forceinline__ void cp_wait0()  { asm volatile("cp.async.wait_group 0;" ::: "memory"); }

__device__ __forceinline__ float ex2(float x) {
    float y;
    asm("ex2.approx.ftz.f32 %0, %1;" : "=f"(y) : "f"(x));
    return y;
}
// pack two fp32 into bf16x2 reg (lo -> low half, hi -> high half)
__device__ __forceinline__ uint32_t pack_bf16(float lo, float hi) {
    uint32_t r;
    asm("cvt.rn.bf16x2.f32 %0, %1, %2;" : "=r"(r) : "f"(hi), "f"(lo));
    return r;
}

// ---------------------------------------------------------------------------
// Split-bf16 HMMA GEMM: C = A[M,K]*B[N,K]^T
// ---------------------------------------------------------------------------
constexpr int LDA    = 40;
constexpr int MAT_SZ = 128 * LDA * 2;
constexpr int STG_SZ = 4 * MAT_SZ;
constexpr int MG_SMEM = 2 * STG_SZ;

__device__ __forceinline__ void mma_gemm_body(
    const __nv_bfloat16* __restrict__ Ahi, const __nv_bfloat16* __restrict__ Alo,
    const __nv_bfloat16* __restrict__ Bhi, const __nv_bfloat16* __restrict__ Blo,
    float* __restrict__ C, int N, int K)
{
    extern __shared__ char smem[];
    const uint32_t sb = smem_u32(smem);

    const int tid = threadIdx.x;
    const int wid = tid >> 5;
    const int lid = tid & 31;
    const int bm  = blockIdx.y * 128;
    const int bn  = blockIdx.x * 128;
    const int wm  = wid >> 2;
    const int wn  = wid & 3;

    const int nIter = K / 32;

    auto load_chunk = [&](int c, int s) {
        const int koff = c * 32;
        const uint32_t st = sb + s * STG_SZ;
        #pragma unroll
        for (int i = tid; i < 512; i += 256) {
            const int r = i >> 2;
            const int q = (i & 3) * 8;
            const uint32_t d = (uint32_t)(r * 80 + q * 2);
            const size_t ga = (size_t)(bm + r) * K + koff + q;
            const size_t gb = (size_t)(bn + r) * K + koff + q;
            cp_async16(st +              d, Ahi + ga);
            cp_async16(st + MAT_SZ     + d, Alo + ga);
            cp_async16(st + 2 * MAT_SZ + d, Bhi + gb);
            cp_async16(st + 3 * MAT_SZ + d, Blo + gb);
        }
        cp_commit();
    };

    float acc[4][4][4] = {};

    load_chunk(0, 0);
    load_chunk(1, 1);

    const int ri = lid & 7;
    const int g  = lid >> 3;
    const int ag_r = ((g & 1) << 3) + ri;
    const int ag_c = (g >> 1) << 3;
    const int bg_r = ((g >> 1) << 3) + ri;
    const int bg_c = (g & 1) << 3;

    for (int c = 0; c < nIter; c++) {
        if (c + 2 < nIter) cp_wait1(); else cp_wait0();
        __syncthreads();

        const uint32_t st  = sb + (uint32_t)(c & 1) * STG_SZ;
        const uint32_t sAh = st;
        const uint32_t sAl = st + MAT_SZ;
        const uint32_t sBh = st + 2 * MAT_SZ;
        const uint32_t sBl = st + 3 * MAT_SZ;

        #pragma unroll
        for (int k16 = 0; k16 < 32; k16 += 16) {
            uint32_t ah[4][4], al[4][4], bh[2][4], bl[2][4];
            #pragma unroll
            for (int mt = 0; mt < 4; mt++) {
                const uint32_t off = (uint32_t)((wm * 64 + mt * 16 + ag_r) * 80
                                                + (k16 + ag_c) * 2);
                ldsm4(ah[mt], sAh + off);
                ldsm4(al[mt], sAl + off);
            }
            #pragma unroll
            for (int np = 0; np < 2; np++) {
                const uint32_t off = (uint32_t)((wn * 32 + np * 16 + bg_r) * 80
                                                + (k16 + bg_c) * 2);
                ldsm4(bh[np], sBh + off);
                ldsm4(bl[np], sBl + off);
            }
            #pragma unroll
            for (int mt = 0; mt < 4; mt++) {
                #pragma unroll
                for (int nt = 0; nt < 4; nt++) {
                    const uint32_t* bhp = &bh[nt >> 1][(nt & 1) * 2];
                    const uint32_t* blp = &bl[nt >> 1][(nt & 1) * 2];
                    mma16816(acc[mt][nt], ah[mt], bhp);
                    mma16816(acc[mt][nt], ah[mt], blp);
                    mma16816(acc[mt][nt], al[mt], bhp);
                }
            }
        }
        __syncthreads();
        if (c + 2 < nIter) load_chunk(c + 2, c & 1);
    }

    const int cr = lid >> 2;
    const int cc = (lid & 3) * 2;
    #pragma unroll
    for (int mt = 0; mt < 4; mt++) {
        #pragma unroll
        for (int nt = 0; nt < 4; nt++) {
            const int row = bm + wm * 64 + mt * 16 + cr;
            const int col = bn + wn * 32 + nt * 8 + cc;
            float2 v0 = {acc[mt][nt][0], acc[mt][nt][1]};
            float2 v1 = {acc[mt][nt][2], acc[mt][nt][3]};
            *(float2*)&C[(size_t)row * N + col]       = v0;
            *(float2*)&C[(size_t)(row + 8) * N + col] = v1;
        }
    }
}

__global__ void __launch_bounds__(256)
mma_gemm(const __nv_bfloat16* __restrict__ Ahi, const __nv_bfloat16* __restrict__ Alo,
         const __nv_bfloat16* __restrict__ Bhi, const __nv_bfloat16* __restrict__ Blo,
         float* __restrict__ C, int N, int K)
{
    mma_gemm_body(Ahi, Alo, Bhi, Blo, C, N, K);
}

__global__ void __launch_bounds__(256)
mma_gemm_qkv(const __nv_bfloat16* __restrict__ xhi, const __nv_bfloat16* __restrict__ xlo,
             const __nv_bfloat16* __restrict__ whi, const __nv_bfloat16* __restrict__ wlo,
             float* __restrict__ Cq, float* __restrict__ Ck, float* __restrict__ Cv)
{
    const int z = blockIdx.z;
    const __nv_bfloat16* Bh = whi + (size_t)z * Dd * Dd;
    const __nv_bfloat16* Bl = wlo + (size_t)z * Dd * Dd;
    float* C = (z == 0) ? Cq : (z == 1) ? Ck : Cv;
    mma_gemm_body(xhi, xlo, Bh, Bl, C, Dd, Dd);
}

// ---------------------------------------------------------------------------
// fp32 -> bf16 hi/lo split
// ---------------------------------------------------------------------------
__global__ void split_f32(const float* __restrict__ src,
                          __nv_bfloat16* __restrict__ hi,
                          __nv_bfloat16* __restrict__ lo, int n4)
{
    int i = blockIdx.x * blockDim.x + threadIdx.x;
    if (i >= n4) return;
    float4 x = ((const float4*)src)[i];
    __nv_bfloat16 h0 = __float2bfloat16(x.x);
    __nv_bfloat16 h1 = __float2bfloat16(x.y);
    __nv_bfloat16 h2 = __float2bfloat16(x.z);
    __nv_bfloat16 h3 = __float2bfloat16(x.w);
    __nv_bfloat16 l0 = __float2bfloat16(x.x - __bfloat162float(h0));
    __nv_bfloat16 l1 = __float2bfloat16(x.y - __bfloat162float(h1));
    __nv_bfloat16 l2 = __float2bfloat16(x.z - __bfloat162float(h2));
    __nv_bfloat16 l3 = __float2bfloat16(x.w - __bfloat162float(h3));
    ((__nv_bfloat162*)hi)[2 * i]     = __nv_bfloat162(h0, h1);
    ((__nv_bfloat162*)hi)[2 * i + 1] = __nv_bfloat162(h2, h3);
    ((__nv_bfloat162*)lo)[2 * i]     = __nv_bfloat162(l0, l1);
    ((__nv_bfloat162*)lo)[2 * i + 1] = __nv_bfloat162(l2, l3);
}

// ---------------------------------------------------------------------------
// RoPE + hi/lo split. Q additionally pre-scaled by 0.125*log2(e) so that
// S-fragments are already in exp2 domain.
// ---------------------------------------------------------------------------
__global__ void rope_split(const float* __restrict__ Q, const float* __restrict__ K,
                           const int* __restrict__ pos,
                           __nv_bfloat16* __restrict__ qhi, __nv_bfloat16* __restrict__ qlo,
                           __nv_bfloat16* __restrict__ khi, __nv_bfloat16* __restrict__ klo)
{
    const int total = MM * Hh * (DKk / 2);
    int idx = blockIdx.x * blockDim.x + threadIdx.x;
    if (idx >= total) return;

    const int j    = idx & 31;
    const int rest = idx >> 5;
    const int h    = rest & (Hh - 1);
    const int row  = rest >> 4;
    const int s    = row & (Ss - 1);

    const float p    = (float)pos[s];
    const float freq = exp2f((float)j * (-2.0f / 64.0f) * 13.28771237954945f);
    float sn, cs;
    sincosf(p * freq, &sn, &cs);

    const int base = row * Dd + h * DKk + 2 * j;
    float2 q = *(float2*)&Q[base];
    float2 k = *(float2*)&K[base];

    constexpr float SCL = 0.18033688011112042f;   // 0.125 * log2(e)
    float q0 = (cs * q.x - sn * q.y) * SCL;
    float q1 = (sn * q.x + cs * q.y) * SCL;
    float k0 = cs * k.x - sn * k.y;
    float k1 = sn * k.x + cs * k.y;

    __nv_bfloat16 qh0 = __float2bfloat16(q0), qh1 = __float2bfloat16(q1);
    __nv_bfloat16 kh0 = __float2bfloat16(k0), kh1 = __float2bfloat16(k1);
    *(__nv_bfloat162*)&qhi[base] = __nv_bfloat162(qh0, qh1);
    *(__nv_bfloat162*)&qlo[base] = __nv_bfloat162(
        __float2bfloat16(q0 - __bfloat162float(qh0)),
        __float2bfloat16(q1 - __bfloat162float(qh1)));
    *(__nv_bfloat162*)&khi[base] = __nv_bfloat162(kh0, kh1);
    *(__nv_bfloat162*)&klo[base] = __nv_bfloat162(
        __float2bfloat16(k0 - __bfloat162float(kh0)),
        __float2bfloat16(k1 - __bfloat162float(kh1)));
}

// ---------------------------------------------------------------------------
// Tensor-core causal flash attention (FA2-style).
// 128 queries/CTA (8 warps x 16 rows), 64-key tiles, split-bf16 3-pass for
// both S=Q*K^T and P*V. Output written directly as bf16 hi/lo.
// ---------------------------------------------------------------------------
constexpr int FA_LD   = 72;                 // bf16 row stride (144 B)
constexpr int FA_MATB = 64 * FA_LD * 2;     // 9216 B per matrix tile
constexpr int FA_STG  = 4 * FA_MATB;        // 36864 B per stage
constexpr int FA_SMEM = 2 * FA_STG;         // 73728 B

__global__ void __launch_bounds__(256)
fa_mma(const __nv_bfloat16* __restrict__ qhi, const __nv_bfloat16* __restrict__ qlo,
       const __nv_bfloat16* __restrict__ khi, const __nv_bfloat16* __restrict__ klo,
       const __nv_bfloat16* __restrict__ vhi, const __nv_bfloat16* __restrict__ vlo,
       __nv_bfloat16* __restrict__ ohi, __nv_bfloat16* __restrict__ olo)
{
    extern __shared__ char smem[];
    const uint32_t sb = smem_u32(smem);

    const int tid = threadIdx.x;
    const int wid = tid >> 5;
    const int lid = tid & 31;
    const int bh  = blockIdx.y;
    const int b   = bh >> 4;
    const int h   = bh & (Hh - 1);
    const int q0  = blockIdx.x * 128;
    const size_t gbase = (size_t)(b * Ss) * Dd + h * DKk;

    const int ri = lid & 7;
    const int g  = lid >> 3;
    const int ag_r = ((g & 1) << 3) + ri;
    const int ag_c = (g >> 1) << 3;
    const int bg_r = ((g >> 1) << 3) + ri;
    const int bg_c = (g & 1) << 3;
    const int tr_r = lid & 15;
    const int tr_c = (lid >> 4) << 3;

    // --- stage Q (hi at sb, lo at sb + 128*144) and load fragments ---
    #pragma unroll
    for (int i = tid; i < 2048; i += 256) {
        const int mat = i >> 10;          // 0=hi, 1=lo
        const int r   = (i >> 3) & 127;
        const int c8  = (i & 7) * 8;
        const __nv_bfloat16* src = (mat ? qlo : qhi) + gbase + (size_t)(q0 + r) * Dd + c8;
        cp_async16(sb + (uint32_t)mat * (128 * 144) + r * 144 + c8 * 2, src);
    }
    cp_commit();
    cp_wait0();
    __syncthreads();

    uint32_t qh[4][4], ql[4][4];
    #pragma unroll
    for (int kt = 0; kt < 4; kt++) {
        const uint32_t off = (uint32_t)((wid * 16 + ag_r) * 144 + (kt * 16 + ag_c) * 2);
        ldsm4(qh[kt], sb + off);
        ldsm4(ql[kt], sb + 128 * 144 + off);
    }
    __syncthreads();        // all Q reads done before buffer reuse

    float o[8][4] = {};
    float m0 = -1e30f, m1 = -1e30f, l0 = 0.f, l1 = 0.f;

    const int ntile = q0 / 64 + 2;

    auto loadKV = [&](int t, int s) {
        const int k0 = t * 64;
        const uint32_t st = sb + (uint32_t)s * FA_STG;
        #pragma unroll
        for (int i = tid; i < 2048; i += 256) {
            const int mat = i >> 9;        // 0=khi 1=klo 2=vhi 3=vlo
            const int r   = (i >> 3) & 63;
            const int c8  = (i & 7) * 8;
            const __nv_bfloat16* gp =
                (mat == 0 ? khi : mat == 1 ? klo : mat == 2 ? vhi : vlo)
                + gbase + (size_t)(k0 + r) * Dd + c8;
            cp_async16(st + (uint32_t)mat * FA_MATB + r * 144 + c8 * 2, gp);
        }
        cp_commit();
    };

    loadKV(0, 0);
    loadKV(1, 1);

    for (int t = 0; t < ntile; t++) {
        if (t + 2 < ntile) cp_wait1(); else cp_wait0();
        __syncthreads();

        const int k0 = t * 64;
        const uint32_t st = sb + (uint32_t)(t & 1) * FA_STG;

        if (k0 <= q0 + wid * 16 + 15) {          // warp has unmasked work here
            float s[8][4] = {};

            // --- S = Q * K^T (3-pass split) ---
            #pragma unroll
            for (int kt = 0; kt < 4; kt++) {
                uint32_t kh[4][4], kl[4][4];
                #pragma unroll
                for (int np = 0; np < 4; np++) {
                    const uint32_t off = (uint32_t)((np * 16 + bg_r) * 144
                                                    + (kt * 16 + bg_c) * 2);
                    ldsm4(kh[np], st + off);
                    ldsm4(kl[np], st + FA_MATB + off);
                }
                #pragma unroll
                for (int np = 0; np < 4; np++) {
                    mma16816(s[2 * np],     qh[kt], &kh[np][0]);
                    mma16816(s[2 * np],     qh[kt], &kl[np][0]);
                    mma16816(s[2 * np],     ql[kt], &kh[np][0]);
                    mma16816(s[2 * np + 1], qh[kt], &kh[np][2]);
                    mma16816(s[2 * np + 1], qh[kt], &kl[np][2]);
                    mma16816(s[2 * np + 1], ql[kt], &kh[np][2]);
                }
            }

            // --- causal mask (diagonal tiles only) ---
            if (k0 + 63 > q0 + wid * 16) {
                const int qr0 = q0 + wid * 16 + (lid >> 2);
                #pragma unroll
                for (int nt = 0; nt < 8; nt++) {
                    #pragma unroll
                    for (int j = 0; j < 4; j++) {
                        const int kc = k0 + nt * 8 + (lid & 3) * 2 + (j & 1);
                        const int qr = qr0 + ((j >> 1) << 3);
                        if (kc > qr) s[nt][j] = -1e30f;
                    }
                }
            }

            // --- online softmax (exp2 domain; Q carried the scale) ---
            float mx0 = -1e30f, mx1 = -1e30f;
            #pragma unroll
            for (int nt = 0; nt < 8; nt++) {
                mx0 = fmaxf(mx0, fmaxf(s[nt][0], s[nt][1]));
                mx1 = fmaxf(mx1, fmaxf(s[nt][2], s[nt][3]));
            }
            mx0 = fmaxf(mx0, __shfl_xor_sync(0xFFFFFFFFu, mx0, 1));
            mx0 = fmaxf(mx0, __shfl_xor_sync(0xFFFFFFFFu, mx0, 2));
            mx1 = fmaxf(mx1, __shfl_xor_sync(0xFFFFFFFFu, mx1, 1));
            mx1 = fmaxf(mx1, __shfl_xor_sync(0xFFFFFFFFu, mx1, 2));

            const float mn0 = fmaxf(m0, mx0);
            const float mn1 = fmaxf(m1, mx1);
            const float c0 = ex2(m0 - mn0);
            const float c1 = ex2(m1 - mn1);
            m0 = mn0; m1 = mn1;

            float sum0 = 0.f, sum1 = 0.f;
            #pragma unroll
            for (int nt = 0; nt < 8; nt++) {
                s[nt][0] = ex2(s[nt][0] - mn0);
                s[nt][1] = ex2(s[nt][1] - mn0);
                s[nt][2] = ex2(s[nt][2] - mn1);
                s[nt][3] = ex2(s[nt][3] - mn1);
                sum0 += s[nt][0] + s[nt][1];
                sum1 += s[nt][2] + s[nt][3];
            }
            sum0 += __shfl_xor_sync(0xFFFFFFFFu, sum0, 1);
            sum0 += __shfl_xor_sync(0xFFFFFFFFu, sum0, 2);
            sum1 += __shfl_xor_sync(0xFFFFFFFFu, sum1, 1);
            sum1 += __shfl_xor_sync(0xFFFFFFFFu, sum1, 2);
            l0 = l0 * c0 + sum0;
            l1 = l1 * c1 + sum1;

            #pragma unroll
            for (int nt = 0; nt < 8; nt++) {
                o[nt][0] *= c0; o[nt][1] *= c0;
                o[nt][2] *= c1; o[nt][3] *= c1;
            }

            // --- O += P * V (3-pass split); P frags built per k-tile ---
            #pragma unroll
            for (int kt = 0; kt < 4; kt++) {
                uint32_t ph[4], pl[4];
                #pragma unroll
                for (int half = 0; half < 2; half++) {
                    const float* sp = s[2 * kt + half];
                    const uint32_t hA = pack_bf16(sp[0], sp[1]);
                    const uint32_t hB = pack_bf16(sp[2], sp[3]);
                    const float lA0 = sp[0] - __uint_as_float(hA << 16);
                    const float lA1 = sp[1] - __uint_as_float(hA & 0xFFFF0000u);
                    const float lB0 = sp[2] - __uint_as_float(hB << 16);
                    const float lB1 = sp[3] - __uint_as_float(hB & 0xFFFF0000u);
                    ph[2 * half]     = hA;
                    ph[2 * half + 1] = hB;
                    pl[2 * half]     = pack_bf16(lA0, lA1);
                    pl[2 * half + 1] = pack_bf16(lB0, lB1);
                }
                uint32_t pA[4] = {ph[0], ph[1], ph[2], ph[3]};
                uint32_t pB[4] = {pl[0], pl[1], pl[2], pl[3]};

                uint32_t vh[4][4], vl[4][4];
                #pragma unroll
                for (int nn = 0; nn < 4; nn++) {
                    const uint32_t off = (uint32_t)((kt * 16 + tr_r) * 144
                                                    + (nn * 16 + tr_c) * 2);
                    ldsm4t(vh[nn], st + 2 * FA_MATB + off);
                    ldsm4t(vl[nn], st + 3 * FA_MATB + off);
                }
                #pragma unroll
                for (int nn = 0; nn < 4; nn++) {
                    mma16816(o[2 * nn],     pA, &vh[nn][0]);
                    mma16816(o[2 * nn],     pA, &vl[nn][0]);
                    mma16816(o[2 * nn],     pB, &vh[nn][0]);
                    mma16816(o[2 * nn + 1], pA, &vh[nn][2]);
                    mma16816(o[2 * nn + 1], pA, &vl[nn][2]);
                    mma16816(o[2 * nn + 1], pB, &vh[nn][2]);
                }
            }
        }

        __syncthreads();
        if (t + 2 < ntile) loadKV(t + 2, t & 1);
    }

    // --- epilogue: normalize + split to bf16 hi/lo, direct store ---
    const float i0 = 1.f / l0;
    const float i1 = 1.f / l1;
    const int r0 = q0 + wid * 16 + (lid >> 2);
    const int cb = (lid & 3) * 2;
    #pragma unroll
    for (int nt = 0; nt < 8; nt++) {
        const int col = h * DKk + nt * 8 + cb;
        {
            const float v0 = o[nt][0] * i0, v1 = o[nt][1] * i0;
            const uint32_t hb = pack_bf16(v0, v1);
            const uint32_t lb = pack_bf16(v0 - __uint_as_float(hb << 16),
                                          v1 - __uint_as_float(hb & 0xFFFF0000u));
            const size_t idx = (size_t)(b * Ss + r0) * Dd + col;
            *(uint32_t*)&ohi[idx] = hb;
            *(uint32_t*)&olo[idx] = lb;
        }
        {
            const float v0 = o[nt][2] * i1, v1 = o[nt][3] * i1;
            const uint32_t hb = pack_bf16(v0, v1);
            const uint32_t lb = pack_bf16(v0 - __uint_as_float(hb << 16),
                                          v1 - __uint_as_float(hb & 0xFFFF0000u));
            const size_t idx = (size_t)(b * Ss + r0 + 8) * Dd + col;
            *(uint32_t*)&ohi[idx] = hb;
            *(uint32_t*)&olo[idx] = lb;
        }
    }
}

// ---------------------------------------------------------------------------
// Launch
// ---------------------------------------------------------------------------
extern "C" void kernel_launch(void* const* d_in, const int* in_sizes, int n_in,
                              void* d_out, int out_size)
{
    const float* x   = (const float*)d_in[0];
    const int*   pos = (const int*)  d_in[1];
    const float* W4[4] = { (const float*)d_in[2], (const float*)d_in[3],
                           (const float*)d_in[4], (const float*)d_in[5] };
    float* out = (float*)d_out;

    float *qp, *kp, *vp;
    cudaGetSymbolAddress((void**)&qp, g_q);
    cudaGetSymbolAddress((void**)&kp, g_k);
    cudaGetSymbolAddress((void**)&vp, g_v);
    __nv_bfloat16 *xhi, *xlo, *whi, *wlo;
    __nv_bfloat16 *qhi, *qlo, *khi, *klo, *vhi, *vlo, *ohi, *olo;
    cudaGetSymbolAddress((void**)&xhi, g_xhi);
    cudaGetSymbolAddress((void**)&xlo, g_xlo);
    cudaGetSymbolAddress((void**)&whi, g_whi);
    cudaGetSymbolAddress((void**)&wlo, g_wlo);
    cudaGetSymbolAddress((void**)&qhi, g_qhi);
    cudaGetSymbolAddress((void**)&qlo, g_qlo);
    cudaGetSymbolAddress((void**)&khi, g_khi);
    cudaGetSymbolAddress((void**)&klo, g_klo);
    cudaGetSymbolAddress((void**)&vhi, g_vhi);
    cudaGetSymbolAddress((void**)&vlo, g_vlo);
    cudaGetSymbolAddress((void**)&ohi, g_ohi);
    cudaGetSymbolAddress((void**)&olo, g_olo);

    cudaFuncSetAttribute(mma_gemm,     cudaFuncAttributeMaxDynamicSharedMemorySize, MG_SMEM);
    cudaFuncSetAttribute(mma_gemm_qkv, cudaFuncAttributeMaxDynamicSharedMemorySize, MG_SMEM);
    cudaFuncSetAttribute(fa_mma,       cudaFuncAttributeMaxDynamicSharedMemorySize, FA_SMEM);

    // Split x and weights
    split_f32<<<(MM * Dd / 4 + 255) / 256, 256>>>(x, xhi, xlo, MM * Dd / 4);
    for (int w = 0; w < 4; w++)
        split_f32<<<(Dd * Dd / 4 + 255) / 256, 256>>>(
            W4[w], whi + (size_t)w * Dd * Dd, wlo + (size_t)w * Dd * Dd, Dd * Dd / 4);

    // Q/K/V projections
    {
        dim3 grid(Dd / 128, MM / 128, 3);
        mma_gemm_qkv<<<grid, 256, MG_SMEM>>>(xhi, xlo, whi, wlo, qp, kp, vp);
    }

    // V split + RoPE/split on Q,K
    split_f32<<<(MM * Dd / 4 + 255) / 256, 256>>>(vp, vhi, vlo, MM * Dd / 4);
    {
        const int total = MM * Hh * (DKk / 2);
        rope_split<<<(total + 255) / 256, 256>>>(qp, kp, pos, qhi, qlo, khi, klo);
    }

    // Tensor-core flash attention
    {
        dim3 fgrid(Ss / 128, Bb * Hh);
        fa_mma<<<fgrid, 256, FA_SMEM>>>(qhi, qlo, khi, klo, vhi, vlo, ohi, olo);
    }

    // Output projection (reads bf16 hi/lo written by FA)
    {
        dim3 grid(Dd / 128, MM / 128);
        mma_gemm<<<grid, 256, MG_SMEM>>>(ohi, olo, whi + 3 * (size_t)Dd * Dd,
                                         wlo + 3 * (size_t)Dd * Dd, out, Dd, Dd);
    }
}

// round 13
// speedup vs baseline: 4.3388x; 1.0270x over previous
#include <cuda_runtime.h>
#include <cuda_bf16.h>
#include <math_constants.h>
#include <cstdint>

// Problem constants
constexpr int Bb  = 2;
constexpr int Ss  = 2048;
constexpr int Dd  = 1024;
constexpr int Hh  = 16;
constexpr int DKk = 64;
constexpr int MM  = Bb * Ss;      // 4096

// bf16 hi/lo scratch
__device__ __nv_bfloat16 g_xhi[MM * Dd];
__device__ __nv_bfloat16 g_xlo[MM * Dd];
__device__ __nv_bfloat16 g_whi[4 * Dd * Dd];   // Q,K,V,O order
__device__ __nv_bfloat16 g_wlo[4 * Dd * Dd];
__device__ __nv_bfloat16 g_qhi[MM * Dd];
__device__ __nv_bfloat16 g_qlo[MM * Dd];
__device__ __nv_bfloat16 g_khi[MM * Dd];
__device__ __nv_bfloat16 g_klo[MM * Dd];
__device__ __nv_bfloat16 g_vhi[MM * Dd];
__device__ __nv_bfloat16 g_vlo[MM * Dd];
__device__ __nv_bfloat16 g_ohi[MM * Dd];
__device__ __nv_bfloat16 g_olo[MM * Dd];
// RoPE cos/sin table: [s][j] -> (cos, sin)
__device__ float2 g_csn[Ss * 32];

// ---------------------------------------------------------------------------
// Warp-level MMA helpers (sm_80+ instructions)
// ---------------------------------------------------------------------------
__device__ __forceinline__ uint32_t smem_u32(const void* p) {
    uint32_t a;
    asm("{ .reg .u64 t; cvta.to.shared.u64 t, %1; cvt.u32.u64 %0, t; }"
        : "=r"(a) : "l"(p));
    return a;
}

__device__ __forceinline__ void mma16816(float* c, const uint32_t* a, const uint32_t* b) {
    asm volatile(
        "mma.sync.aligned.m16n8k16.row.col.f32.bf16.bf16.f32 "
        "{%0,%1,%2,%3}, {%4,%5,%6,%7}, {%8,%9}, {%0,%1,%2,%3};"
        : "+f"(c[0]), "+f"(c[1]), "+f"(c[2]), "+f"(c[3])
        : "r"(a[0]), "r"(a[1]), "r"(a[2]), "r"(a[3]), "r"(b[0]), "r"(b[1]));
}

__device__ __forceinline__ void ldsm4(uint32_t* r, uint32_t a) {
    asm volatile("ldmatrix.sync.aligned.m8n8.x4.shared.b16 {%0,%1,%2,%3}, [%4];"
        : "=r"(r[0]), "=r"(r[1]), "=r"(r[2]), "=r"(r[3]) : "r"(a));
}
__device__ __forceinline__ void ldsm4t(uint32_t* r, uint32_t a) {
    asm volatile("ldmatrix.sync.aligned.m8n8.x4.trans.shared.b16 {%0,%1,%2,%3}, [%4];"
        : "=r"(r[0]), "=r"(r[1]), "=r"(r[2]), "=r"(r[3]) : "r"(a));
}

__device__ __forceinline__ void cp_async16(uint32_t dst, const void* src) {
    asm volatile("cp.async.cg.shared.global [%0], [%1], 16;" :: "r"(dst), "l"(src) : "memory");
}
__device__ __forceinline__ void cp_commit() { asm volatile("cp.async.commit_group;" ::: "memory"); }
__device__ __forceinline__ void cp_wait1()  { asm volatile("cp.async.wait_group 1;" ::: "memory"); }
__device__ __forceinline__ void cp_wait0()  { asm volatile("cp.async.wait_group 0;" ::: "memory"); }

__device__ __forceinline__ float ex2(float x) {
    float y;
    asm("ex2.approx.ftz.f32 %0, %1;" : "=f"(y) : "f"(x));
    return y;
}
// pack two fp32 into bf16x2 reg (first arg -> low half, second -> high half)
__device__ __forceinline__ uint32_t pack_bf16(float lo, float hi) {
    uint32_t r;
    asm("cvt.rn.bf16x2.f32 %0, %1, %2;" : "=r"(r) : "f"(hi), "f"(lo));
    return r;
}

// ---------------------------------------------------------------------------
// Split-bf16 HMMA GEMM core: acc = A[M,K]*B[N,K]^T (3-pass hi/lo)
// 128x128 tile, BK=32, 8 warps (64x32), cp.async double buffer.
// ---------------------------------------------------------------------------
constexpr int LDA    = 40;
constexpr int MAT_SZ = 128 * LDA * 2;
constexpr int STG_SZ = 4 * MAT_SZ;
constexpr int MG_SMEM = 2 * STG_SZ;

__device__ __forceinline__ void mma_gemm_core(
    const __nv_bfloat16* __restrict__ Ahi, const __nv_bfloat16* __restrict__ Alo,
    const __nv_bfloat16* __restrict__ Bhi, const __nv_bfloat16* __restrict__ Blo,
    int K, float acc[4][4][4])
{
    extern __shared__ char smem[];
    const uint32_t sb = smem_u32(smem);

    const int tid = threadIdx.x;
    const int wid = tid >> 5;
    const int lid = tid & 31;
    const int bm  = blockIdx.y * 128;
    const int bn  = blockIdx.x * 128;
    const int wm  = wid >> 2;
    const int wn  = wid & 3;

    const int nIter = K / 32;

    auto load_chunk = [&](int c, int s) {
        const int koff = c * 32;
        const uint32_t st = sb + s * STG_SZ;
        #pragma unroll
        for (int i = tid; i < 512; i += 256) {
            const int r = i >> 2;
            const int q = (i & 3) * 8;
            const uint32_t d = (uint32_t)(r * 80 + q * 2);
            const size_t ga = (size_t)(bm + r) * K + koff + q;
            const size_t gb = (size_t)(bn + r) * K + koff + q;
            cp_async16(st +              d, Ahi + ga);
            cp_async16(st + MAT_SZ     + d, Alo + ga);
            cp_async16(st + 2 * MAT_SZ + d, Bhi + gb);
            cp_async16(st + 3 * MAT_SZ + d, Blo + gb);
        }
        cp_commit();
    };

    load_chunk(0, 0);
    load_chunk(1, 1);

    const int ri = lid & 7;
    const int g  = lid >> 3;
    const int ag_r = ((g & 1) << 3) + ri;
    const int ag_c = (g >> 1) << 3;
    const int bg_r = ((g >> 1) << 3) + ri;
    const int bg_c = (g & 1) << 3;

    for (int c = 0; c < nIter; c++) {
        if (c + 2 < nIter) cp_wait1(); else cp_wait0();
        __syncthreads();

        const uint32_t st  = sb + (uint32_t)(c & 1) * STG_SZ;
        const uint32_t sAh = st;
        const uint32_t sAl = st + MAT_SZ;
        const uint32_t sBh = st + 2 * MAT_SZ;
        const uint32_t sBl = st + 3 * MAT_SZ;

        #pragma unroll
        for (int k16 = 0; k16 < 32; k16 += 16) {
            uint32_t ah[4][4], al[4][4], bh[2][4], bl[2][4];
            #pragma unroll
            for (int mt = 0; mt < 4; mt++) {
                const uint32_t off = (uint32_t)((wm * 64 + mt * 16 + ag_r) * 80
                                                + (k16 + ag_c) * 2);
                ldsm4(ah[mt], sAh + off);
                ldsm4(al[mt], sAl + off);
            }
            #pragma unroll
            for (int np = 0; np < 2; np++) {
                const uint32_t off = (uint32_t)((wn * 32 + np * 16 + bg_r) * 80
                                                + (k16 + bg_c) * 2);
                ldsm4(bh[np], sBh + off);
                ldsm4(bl[np], sBl + off);
            }
            #pragma unroll
            for (int mt = 0; mt < 4; mt++) {
                #pragma unroll
                for (int nt = 0; nt < 4; nt++) {
                    const uint32_t* bhp = &bh[nt >> 1][(nt & 1) * 2];
                    const uint32_t* blp = &bl[nt >> 1][(nt & 1) * 2];
                    mma16816(acc[mt][nt], ah[mt], bhp);
                    mma16816(acc[mt][nt], ah[mt], blp);
                    mma16816(acc[mt][nt], al[mt], bhp);
                }
            }
        }
        __syncthreads();
        if (c + 2 < nIter) load_chunk(c + 2, c & 1);
    }
}

// Plain fp32-output GEMM (used for the final O projection into d_out)
__global__ void __launch_bounds__(256)
mma_gemm(const __nv_bfloat16* __restrict__ Ahi, const __nv_bfloat16* __restrict__ Alo,
         const __nv_bfloat16* __restrict__ Bhi, const __nv_bfloat16* __restrict__ Blo,
         float* __restrict__ C, int N, int K)
{
    float acc[4][4][4] = {};
    mma_gemm_core(Ahi, Alo, Bhi, Blo, K, acc);

    const int tid = threadIdx.x;
    const int wid = tid >> 5;
    const int lid = tid & 31;
    const int bm  = blockIdx.y * 128;
    const int bn  = blockIdx.x * 128;
    const int wm  = wid >> 2;
    const int wn  = wid & 3;
    const int cr  = lid >> 2;
    const int cc  = (lid & 3) * 2;
    #pragma unroll
    for (int mt = 0; mt < 4; mt++) {
        #pragma unroll
        for (int nt = 0; nt < 4; nt++) {
            const int row = bm + wm * 64 + mt * 16 + cr;
            const int col = bn + wn * 32 + nt * 8 + cc;
            float2 v0 = {acc[mt][nt][0], acc[mt][nt][1]};
            float2 v1 = {acc[mt][nt][2], acc[mt][nt][3]};
            *(float2*)&C[(size_t)row * N + col]       = v0;
            *(float2*)&C[(size_t)(row + 8) * N + col] = v1;
        }
    }
}

// Fused QKV projection: z=0 -> Q (rope + SCL + split), z=1 -> K (rope + split),
// z=2 -> V (split). Outputs bf16 hi/lo directly; no fp32 scratch.
__global__ void __launch_bounds__(256)
mma_gemm_qkv(const __nv_bfloat16* __restrict__ xhi, const __nv_bfloat16* __restrict__ xlo,
             const __nv_bfloat16* __restrict__ whi, const __nv_bfloat16* __restrict__ wlo,
             __nv_bfloat16* __restrict__ qhi, __nv_bfloat16* __restrict__ qlo,
             __nv_bfloat16* __restrict__ khi, __nv_bfloat16* __restrict__ klo,
             __nv_bfloat16* __restrict__ vhi, __nv_bfloat16* __restrict__ vlo)
{
    const int z = blockIdx.z;
    const __nv_bfloat16* Bh = whi + (size_t)z * Dd * Dd;
    const __nv_bfloat16* Bl = wlo + (size_t)z * Dd * Dd;

    float acc[4][4][4] = {};
    mma_gemm_core(xhi, xlo, Bh, Bl, Dd, acc);

    __nv_bfloat16* dhi = (z == 0) ? qhi : (z == 1) ? khi : vhi;
    __nv_bfloat16* dlo = (z == 0) ? qlo : (z == 1) ? klo : vlo;
    const float scale = (z == 0) ? 0.18033688011112042f : 1.0f;  // 0.125*log2(e)

    const int tid = threadIdx.x;
    const int wid = tid >> 5;
    const int lid = tid & 31;
    const int bm  = blockIdx.y * 128;
    const int bn  = blockIdx.x * 128;
    const int wm  = wid >> 2;
    const int wn  = wid & 3;
    const int cr  = lid >> 2;
    const int cc  = (lid & 3) * 2;

    #pragma unroll
    for (int mt = 0; mt < 4; mt++) {
        #pragma unroll
        for (int nt = 0; nt < 4; nt++) {
            const int row0 = bm + wm * 64 + mt * 16 + cr;
            const int col  = bn + wn * 32 + nt * 8 + cc;   // even -> rope pair (col, col+1)
            float a0 = acc[mt][nt][0], a1 = acc[mt][nt][1];   // row0
            float b0 = acc[mt][nt][2], b1 = acc[mt][nt][3];   // row0 + 8
            if (z < 2) {
                const int j = (col & 63) >> 1;
                const float2 cs0 = g_csn[(row0 & (Ss - 1)) * 32 + j];
                const float2 cs1 = g_csn[((row0 + 8) & (Ss - 1)) * 32 + j];
                float t0 = cs0.x * a0 - cs0.y * a1;
                float t1 = cs0.y * a0 + cs0.x * a1;
                a0 = t0 * scale; a1 = t1 * scale;
                t0 = cs1.x * b0 - cs1.y * b1;
                t1 = cs1.y * b0 + cs1.x * b1;
                b0 = t0 * scale; b1 = t1 * scale;
            }
            {
                const uint32_t hb = pack_bf16(a0, a1);
                const uint32_t lb = pack_bf16(a0 - __uint_as_float(hb << 16),
                                              a1 - __uint_as_float(hb & 0xFFFF0000u));
                const size_t idx = (size_t)row0 * Dd + col;
                *(uint32_t*)&dhi[idx] = hb;
                *(uint32_t*)&dlo[idx] = lb;
            }
            {
                const uint32_t hb = pack_bf16(b0, b1);
                const uint32_t lb = pack_bf16(b0 - __uint_as_float(hb << 16),
                                              b1 - __uint_as_float(hb & 0xFFFF0000u));
                const size_t idx = (size_t)(row0 + 8) * Dd + col;
                *(uint32_t*)&dhi[idx] = hb;
                *(uint32_t*)&dlo[idx] = lb;
            }
        }
    }
}

// ---------------------------------------------------------------------------
// fp32 -> bf16 hi/lo split (x input)
// ---------------------------------------------------------------------------
__global__ void split_f32(const float* __restrict__ src,
                          __nv_bfloat16* __restrict__ hi,
                          __nv_bfloat16* __restrict__ lo, int n4)
{
    int i = blockIdx.x * blockDim.x + threadIdx.x;
    if (i >= n4) return;
    float4 x = ((const float4*)src)[i];
    __nv_bfloat16 h0 = __float2bfloat16(x.x);
    __nv_bfloat16 h1 = __float2bfloat16(x.y);
    __nv_bfloat16 h2 = __float2bfloat16(x.z);
    __nv_bfloat16 h3 = __float2bfloat16(x.w);
    __nv_bfloat16 l0 = __float2bfloat16(x.x - __bfloat162float(h0));
    __nv_bfloat16 l1 = __float2bfloat16(x.y - __bfloat162float(h1));
    __nv_bfloat16 l2 = __float2bfloat16(x.z - __bfloat162float(h2));
    __nv_bfloat16 l3 = __float2bfloat16(x.w - __bfloat162float(h3));
    ((__nv_bfloat162*)hi)[2 * i]     = __nv_bfloat162(h0, h1);
    ((__nv_bfloat162*)hi)[2 * i + 1] = __nv_bfloat162(h2, h3);
    ((__nv_bfloat162*)lo)[2 * i]     = __nv_bfloat162(l0, l1);
    ((__nv_bfloat162*)lo)[2 * i + 1] = __nv_bfloat162(l2, l3);
}

// All four weights in one launch (z selects the weight)
__global__ void split_w4(const float* __restrict__ w0, const float* __restrict__ w1,
                         const float* __restrict__ w2, const float* __restrict__ w3,
                         __nv_bfloat16* __restrict__ hi, __nv_bfloat16* __restrict__ lo)
{
    const int z = blockIdx.z;
    const float* src = (z == 0) ? w0 : (z == 1) ? w1 : (z == 2) ? w2 : w3;
    const int n4 = Dd * Dd / 4;
    int i = blockIdx.x * blockDim.x + threadIdx.x;
    if (i >= n4) return;
    float4 x = ((const float4*)src)[i];
    __nv_bfloat16* hz = hi + (size_t)z * Dd * Dd;
    __nv_bfloat16* lz = lo + (size_t)z * Dd * Dd;
    __nv_bfloat16 h0 = __float2bfloat16(x.x);
    __nv_bfloat16 h1 = __float2bfloat16(x.y);
    __nv_bfloat16 h2 = __float2bfloat16(x.z);
    __nv_bfloat16 h3 = __float2bfloat16(x.w);
    __nv_bfloat16 l0 = __float2bfloat16(x.x - __bfloat162float(h0));
    __nv_bfloat16 l1 = __float2bfloat16(x.y - __bfloat162float(h1));
    __nv_bfloat16 l2 = __float2bfloat16(x.z - __bfloat162float(h2));
    __nv_bfloat16 l3 = __float2bfloat16(x.w - __bfloat162float(h3));
    ((__nv_bfloat162*)hz)[2 * i]     = __nv_bfloat162(h0, h1);
    ((__nv_bfloat162*)hz)[2 * i + 1] = __nv_bfloat162(h2, h3);
    ((__nv_bfloat162*)lz)[2 * i]     = __nv_bfloat162(l0, l1);
    ((__nv_bfloat162*)lz)[2 * i + 1] = __nv_bfloat162(l2, l3);
}

// RoPE cos/sin table from token positions
__global__ void rope_cs(const int* __restrict__ pos)
{
    int idx = blockIdx.x * blockDim.x + threadIdx.x;
    if (idx >= Ss * 32) return;
    const int s = idx >> 5;
    const int j = idx & 31;
    const float p    = (float)pos[s];
    const float freq = exp2f((float)j * (-2.0f / 64.0f) * 13.28771237954945f);
    float sn, cs;
    sincosf(p * freq, &sn, &cs);
    g_csn[idx] = make_float2(cs, sn);
}

// ---------------------------------------------------------------------------
// Tensor-core causal flash attention (R8 winner, unchanged)
// ---------------------------------------------------------------------------
constexpr int FA_LD   = 72;
constexpr int FA_MATB = 64 * FA_LD * 2;
constexpr int FA_STG  = 4 * FA_MATB;
constexpr int FA_SMEM = 2 * FA_STG;

__global__ void __launch_bounds__(256)
fa_mma(const __nv_bfloat16* __restrict__ qhi, const __nv_bfloat16* __restrict__ qlo,
       const __nv_bfloat16* __restrict__ khi, const __nv_bfloat16* __restrict__ klo,
       const __nv_bfloat16* __restrict__ vhi, const __nv_bfloat16* __restrict__ vlo,
       __nv_bfloat16* __restrict__ ohi, __nv_bfloat16* __restrict__ olo)
{
    extern __shared__ char smem[];
    const uint32_t sb = smem_u32(smem);

    const int tid = threadIdx.x;
    const int wid = tid >> 5;
    const int lid = tid & 31;
    const int bh  = blockIdx.y;
    const int b   = bh >> 4;
    const int h   = bh & (Hh - 1);
    const int q0  = blockIdx.x * 128;
    const size_t gbase = (size_t)(b * Ss) * Dd + h * DKk;

    const int ri = lid & 7;
    const int g  = lid >> 3;
    const int ag_r = ((g & 1) << 3) + ri;
    const int ag_c = (g >> 1) << 3;
    const int bg_r = ((g >> 1) << 3) + ri;
    const int bg_c = (g & 1) << 3;
    const int tr_r = lid & 15;
    const int tr_c = (lid >> 4) << 3;

    #pragma unroll
    for (int i = tid; i < 2048; i += 256) {
        const int mat = i >> 10;
        const int r   = (i >> 3) & 127;
        const int c8  = (i & 7) * 8;
        const __nv_bfloat16* src = (mat ? qlo : qhi) + gbase + (size_t)(q0 + r) * Dd + c8;
        cp_async16(sb + (uint32_t)mat * (128 * 144) + r * 144 + c8 * 2, src);
    }
    cp_commit();
    cp_wait0();
    __syncthreads();

    uint32_t qh[4][4], ql[4][4];
    #pragma unroll
    for (int kt = 0; kt < 4; kt++) {
        const uint32_t off = (uint32_t)((wid * 16 + ag_r) * 144 + (kt * 16 + ag_c) * 2);
        ldsm4(qh[kt], sb + off);
        ldsm4(ql[kt], sb + 128 * 144 + off);
    }
    __syncthreads();

    float o[8][4] = {};
    float m0 = -1e30f, m1 = -1e30f, l0 = 0.f, l1 = 0.f;

    const int ntile = q0 / 64 + 2;

    auto loadKV = [&](int t, int s) {
        const int k0 = t * 64;
        const uint32_t st = sb + (uint32_t)s * FA_STG;
        #pragma unroll
        for (int i = tid; i < 2048; i += 256) {
            const int mat = i >> 9;
            const int r   = (i >> 3) & 63;
            const int c8  = (i & 7) * 8;
            const __nv_bfloat16* gp =
                (mat == 0 ? khi : mat == 1 ? klo : mat == 2 ? vhi : vlo)
                + gbase + (size_t)(k0 + r) * Dd + c8;
            cp_async16(st + (uint32_t)mat * FA_MATB + r * 144 + c8 * 2, gp);
        }
        cp_commit();
    };

    loadKV(0, 0);
    loadKV(1, 1);

    for (int t = 0; t < ntile; t++) {
        if (t + 2 < ntile) cp_wait1(); else cp_wait0();
        __syncthreads();

        const int k0 = t * 64;
        const uint32_t st = sb + (uint32_t)(t & 1) * FA_STG;

        if (k0 <= q0 + wid * 16 + 15) {
            float s[8][4] = {};

            #pragma unroll
            for (int kt = 0; kt < 4; kt++) {
                uint32_t kh[4][4], kl[4][4];
                #pragma unroll
                for (int np = 0; np < 4; np++) {
                    const uint32_t off = (uint32_t)((np * 16 + bg_r) * 144
                                                    + (kt * 16 + bg_c) * 2);
                    ldsm4(kh[np], st + off);
                    ldsm4(kl[np], st + FA_MATB + off);
                }
                #pragma unroll
                for (int np = 0; np < 4; np++) {
                    mma16816(s[2 * np],     qh[kt], &kh[np][0]);
                    mma16816(s[2 * np],     qh[kt], &kl[np][0]);
                    mma16816(s[2 * np],     ql[kt], &kh[np][0]);
                    mma16816(s[2 * np + 1], qh[kt], &kh[np][2]);
                    mma16816(s[2 * np + 1], qh[kt], &kl[np][2]);
                    mma16816(s[2 * np + 1], ql[kt], &kh[np][2]);
                }
            }

            if (k0 + 63 > q0 + wid * 16) {
                const int qr0 = q0 + wid * 16 + (lid >> 2);
                #pragma unroll
                for (int nt = 0; nt < 8; nt++) {
                    #pragma unroll
                    for (int j = 0; j < 4; j++) {
                        const int kc = k0 + nt * 8 + (lid & 3) * 2 + (j & 1);
                        const int qr = qr0 + ((j >> 1) << 3);
                        if (kc > qr) s[nt][j] = -1e30f;
                    }
                }
            }

            float mx0 = -1e30f, mx1 = -1e30f;
            #pragma unroll
            for (int nt = 0; nt < 8; nt++) {
                mx0 = fmaxf(mx0, fmaxf(s[nt][0], s[nt][1]));
                mx1 = fmaxf(mx1, fmaxf(s[nt][2], s[nt][3]));
            }
            mx0 = fmaxf(mx0, __shfl_xor_sync(0xFFFFFFFFu, mx0, 1));
            mx0 = fmaxf(mx0, __shfl_xor_sync(0xFFFFFFFFu, mx0, 2));
            mx1 = fmaxf(mx1, __shfl_xor_sync(0xFFFFFFFFu, mx1, 1));
            mx1 = fmaxf(mx1, __shfl_xor_sync(0xFFFFFFFFu, mx1, 2));

            const float mn0 = fmaxf(m0, mx0);
            const float mn1 = fmaxf(m1, mx1);
            const float c0 = ex2(m0 - mn0);
            const float c1 = ex2(m1 - mn1);
            m0 = mn0; m1 = mn1;

            float sum0 = 0.f, sum1 = 0.f;
            #pragma unroll
            for (int nt = 0; nt < 8; nt++) {
                s[nt][0] = ex2(s[nt][0] - mn0);
                s[nt][1] = ex2(s[nt][1] - mn0);
                s[nt][2] = ex2(s[nt][2] - mn1);
                s[nt][3] = ex2(s[nt][3] - mn1);
                sum0 += s[nt][0] + s[nt][1];
                sum1 += s[nt][2] + s[nt][3];
            }
            sum0 += __shfl_xor_sync(0xFFFFFFFFu, sum0, 1);
            sum0 += __shfl_xor_sync(0xFFFFFFFFu, sum0, 2);
            sum1 += __shfl_xor_sync(0xFFFFFFFFu, sum1, 1);
            sum1 += __shfl_xor_sync(0xFFFFFFFFu, sum1, 2);
            l0 = l0 * c0 + sum0;
            l1 = l1 * c1 + sum1;

            #pragma unroll
            for (int nt = 0; nt < 8; nt++) {
                o[nt][0] *= c0; o[nt][1] *= c0;
                o[nt][2] *= c1; o[nt][3] *= c1;
            }

            #pragma unroll
            for (int kt = 0; kt < 4; kt++) {
                uint32_t ph[4], pl[4];
                #pragma unroll
                for (int half = 0; half < 2; half++) {
                    const float* sp = s[2 * kt + half];
                    const uint32_t hA = pack_bf16(sp[0], sp[1]);
                    const uint32_t hB = pack_bf16(sp[2], sp[3]);
                    const float lA0 = sp[0] - __uint_as_float(hA << 16);
                    const float lA1 = sp[1] - __uint_as_float(hA & 0xFFFF0000u);
                    const float lB0 = sp[2] - __uint_as_float(hB << 16);
                    const float lB1 = sp[3] - __uint_as_float(hB & 0xFFFF0000u);
                    ph[2 * half]     = hA;
                    ph[2 * half + 1] = hB;
                    pl[2 * half]     = pack_bf16(lA0, lA1);
                    pl[2 * half + 1] = pack_bf16(lB0, lB1);
                }
                uint32_t pA[4] = {ph[0], ph[1], ph[2], ph[3]};
                uint32_t pB[4] = {pl[0], pl[1], pl[2], pl[3]};

                uint32_t vh[4][4], vl[4][4];
                #pragma unroll
                for (int nn = 0; nn < 4; nn++) {
                    const uint32_t off = (uint32_t)((kt * 16 + tr_r) * 144
                                                    + (nn * 16 + tr_c) * 2);
                    ldsm4t(vh[nn], st + 2 * FA_MATB + off);
                    ldsm4t(vl[nn], st + 3 * FA_MATB + off);
                }
                #pragma unroll
                for (int nn = 0; nn < 4; nn++) {
                    mma16816(o[2 * nn],     pA, &vh[nn][0]);
                    mma16816(o[2 * nn],     pA, &vl[nn][0]);
                    mma16816(o[2 * nn],     pB, &vh[nn][0]);
                    mma16816(o[2 * nn + 1], pA, &vh[nn][2]);
                    mma16816(o[2 * nn + 1], pA, &vl[nn][2]);
                    mma16816(o[2 * nn + 1], pB, &vh[nn][2]);
                }
            }
        }

        __syncthreads();
        if (t + 2 < ntile) loadKV(t + 2, t & 1);
    }

    const float i0 = 1.f / l0;
    const float i1 = 1.f / l1;
    const int r0 = q0 + wid * 16 + (lid >> 2);
    const int cb = (lid & 3) * 2;
    #pragma unroll
    for (int nt = 0; nt < 8; nt++) {
        const int col = h * DKk + nt * 8 + cb;
        {
            const float v0 = o[nt][0] * i0, v1 = o[nt][1] * i0;
            const uint32_t hb = pack_bf16(v0, v1);
            const uint32_t lb = pack_bf16(v0 - __uint_as_float(hb << 16),
                                          v1 - __uint_as_float(hb & 0xFFFF0000u));
            const size_t idx = (size_t)(b * Ss + r0) * Dd + col;
            *(uint32_t*)&ohi[idx] = hb;
            *(uint32_t*)&olo[idx] = lb;
        }
        {
            const float v0 = o[nt][2] * i1, v1 = o[nt][3] * i1;
            const uint32_t hb = pack_bf16(v0, v1);
            const uint32_t lb = pack_bf16(v0 - __uint_as_float(hb << 16),
                                          v1 - __uint_as_float(hb & 0xFFFF0000u));
            const size_t idx = (size_t)(b * Ss + r0 + 8) * Dd + col;
            *(uint32_t*)&ohi[idx] = hb;
            *(uint32_t*)&olo[idx] = lb;
        }
    }
}

// ---------------------------------------------------------------------------
// Launch
// ---------------------------------------------------------------------------
extern "C" void kernel_launch(void* const* d_in, const int* in_sizes, int n_in,
                              void* d_out, int out_size)
{
    const float* x   = (const float*)d_in[0];
    const int*   pos = (const int*)  d_in[1];
    const float* WQ  = (const float*)d_in[2];
    const float* WK  = (const float*)d_in[3];
    const float* WV  = (const float*)d_in[4];
    const float* WO  = (const float*)d_in[5];
    float* out = (float*)d_out;

    __nv_bfloat16 *xhi, *xlo, *whi, *wlo;
    __nv_bfloat16 *qhi, *qlo, *khi, *klo, *vhi, *vlo, *ohi, *olo;
    cudaGetSymbolAddress((void**)&xhi, g_xhi);
    cudaGetSymbolAddress((void**)&xlo, g_xlo);
    cudaGetSymbolAddress((void**)&whi, g_whi);
    cudaGetSymbolAddress((void**)&wlo, g_wlo);
    cudaGetSymbolAddress((void**)&qhi, g_qhi);
    cudaGetSymbolAddress((void**)&qlo, g_qlo);
    cudaGetSymbolAddress((void**)&khi, g_khi);
    cudaGetSymbolAddress((void**)&klo, g_klo);
    cudaGetSymbolAddress((void**)&vhi, g_vhi);
    cudaGetSymbolAddress((void**)&vlo, g_vlo);
    cudaGetSymbolAddress((void**)&ohi, g_ohi);
    cudaGetSymbolAddress((void**)&olo, g_olo);

    cudaFuncSetAttribute(mma_gemm,     cudaFuncAttributeMaxDynamicSharedMemorySize, MG_SMEM);
    cudaFuncSetAttribute(mma_gemm_qkv, cudaFuncAttributeMaxDynamicSharedMemorySize, MG_SMEM);
    cudaFuncSetAttribute(fa_mma,       cudaFuncAttributeMaxDynamicSharedMemorySize, FA_SMEM);

    // 1. split x
    split_f32<<<(MM * Dd / 4 + 255) / 256, 256>>>(x, xhi, xlo, MM * Dd / 4);
    // 2. split all 4 weights (one launch)
    {
        dim3 grid((Dd * Dd / 4 + 255) / 256, 1, 4);
        split_w4<<<grid, 256>>>(WQ, WK, WV, WO, whi, wlo);
    }
    // 3. RoPE cos/sin table
    rope_cs<<<(Ss * 32 + 255) / 256, 256>>>(pos);
    // 4. fused QKV projection + RoPE + split (no fp32 scratch)
    {
        dim3 grid(Dd / 128, MM / 128, 3);
        mma_gemm_qkv<<<grid, 256, MG_SMEM>>>(xhi, xlo, whi, wlo,
                                             qhi, qlo, khi, klo, vhi, vlo);
    }
    // 5. tensor-core flash attention
    {
        dim3 fgrid(Ss / 128, Bb * Hh);
        fa_mma<<<fgrid, 256, FA_SMEM>>>(qhi, qlo, khi, klo, vhi, vlo, ohi, olo);
    }
    // 6. output projection
    {
        dim3 grid(Dd / 128, MM / 128);
        mma_gemm<<<grid, 256, MG_SMEM>>>(ohi, olo, whi + 3 * (size_t)Dd * Dd,
                                         wlo + 3 * (size_t)Dd * Dd, out, Dd, Dd);
    }
}

// round 16
// speedup vs baseline: 5.0929x; 1.1738x over previous
#include <cuda_runtime.h>
#include <cuda_bf16.h>
#include <math_constants.h>
#include <cstdint>

// Problem constants
constexpr int Bb  = 2;
constexpr int Ss  = 2048;
constexpr int Dd  = 1024;
constexpr int Hh  = 16;
constexpr int DKk = 64;
constexpr int MM  = Bb * Ss;      // 4096

// tf32-rounded fp32 operands
__device__ float g_xt[MM * Dd];
__device__ float g_wt[4 * Dd * Dd];    // Q,K,V,O order
__device__ float g_of[MM * Dd];        // FA output (tf32-rounded)
// bf16 hi/lo Q/K/V for flash attention
__device__ __nv_bfloat16 g_qhi[MM * Dd];
__device__ __nv_bfloat16 g_qlo[MM * Dd];
__device__ __nv_bfloat16 g_khi[MM * Dd];
__device__ __nv_bfloat16 g_klo[MM * Dd];
__device__ __nv_bfloat16 g_vhi[MM * Dd];
__device__ __nv_bfloat16 g_vlo[MM * Dd];
// RoPE cos/sin table: [s][j] -> (cos, sin)
__device__ float2 g_csn[Ss * 32];

// ---------------------------------------------------------------------------
// Helpers
// ---------------------------------------------------------------------------
__device__ __forceinline__ uint32_t smem_u32(const void* p) {
    uint32_t a;
    asm("{ .reg .u64 t; cvta.to.shared.u64 t, %1; cvt.u32.u64 %0, t; }"
        : "=r"(a) : "l"(p));
    return a;
}
__device__ __forceinline__ float to_tf32(float x) {
    float y;
    asm("cvt.rna.tf32.f32 %0, %1;" : "=f"(y) : "f"(x));
    return y;
}
__device__ __forceinline__ uint32_t lds32(uint32_t a) {
    uint32_t v;
    asm volatile("ld.shared.b32 %0, [%1];" : "=r"(v) : "r"(a));
    return v;
}
__device__ __forceinline__ void mma16808(float* c, const uint32_t* a, const uint32_t* b) {
    asm volatile(
        "mma.sync.aligned.m16n8k8.row.col.f32.tf32.tf32.f32 "
        "{%0,%1,%2,%3}, {%4,%5,%6,%7}, {%8,%9}, {%0,%1,%2,%3};"
        : "+f"(c[0]), "+f"(c[1]), "+f"(c[2]), "+f"(c[3])
        : "r"(a[0]), "r"(a[1]), "r"(a[2]), "r"(a[3]), "r"(b[0]), "r"(b[1]));
}
__device__ __forceinline__ void mma16816(float* c, const uint32_t* a, const uint32_t* b) {
    asm volatile(
        "mma.sync.aligned.m16n8k16.row.col.f32.bf16.bf16.f32 "
        "{%0,%1,%2,%3}, {%4,%5,%6,%7}, {%8,%9}, {%0,%1,%2,%3};"
        : "+f"(c[0]), "+f"(c[1]), "+f"(c[2]), "+f"(c[3])
        : "r"(a[0]), "r"(a[1]), "r"(a[2]), "r"(a[3]), "r"(b[0]), "r"(b[1]));
}
__device__ __forceinline__ void ldsm4(uint32_t* r, uint32_t a) {
    asm volatile("ldmatrix.sync.aligned.m8n8.x4.shared.b16 {%0,%1,%2,%3}, [%4];"
        : "=r"(r[0]), "=r"(r[1]), "=r"(r[2]), "=r"(r[3]) : "r"(a));
}
__device__ __forceinline__ void ldsm4t(uint32_t* r, uint32_t a) {
    asm volatile("ldmatrix.sync.aligned.m8n8.x4.trans.shared.b16 {%0,%1,%2,%3}, [%4];"
        : "=r"(r[0]), "=r"(r[1]), "=r"(r[2]), "=r"(r[3]) : "r"(a));
}
__device__ __forceinline__ void cp_async16(uint32_t dst, const void* src) {
    asm volatile("cp.async.cg.shared.global [%0], [%1], 16;" :: "r"(dst), "l"(src) : "memory");
}
__device__ __forceinline__ void cp_commit() { asm volatile("cp.async.commit_group;" ::: "memory"); }
__device__ __forceinline__ void cp_wait1()  { asm volatile("cp.async.wait_group 1;" ::: "memory"); }
__device__ __forceinline__ void cp_wait0()  { asm volatile("cp.async.wait_group 0;" ::: "memory"); }
__device__ __forceinline__ float ex2(float x) {
    float y;
    asm("ex2.approx.ftz.f32 %0, %1;" : "=f"(y) : "f"(x));
    return y;
}
__device__ __forceinline__ uint32_t pack_bf16(float lo, float hi) {
    uint32_t r;
    asm("cvt.rn.bf16x2.f32 %0, %1, %2;" : "=r"(r) : "f"(hi), "f"(lo));
    return r;
}

// ---------------------------------------------------------------------------
// Single-pass TF32 GEMM core: acc = A[M,K]*B[N,K]^T, operands fp32 (tf32-rounded)
// 128x128 tile, BK=32, 8 warps (64x32 warp tile), cp.async double buffer.
// smem rows padded to 144 B (36 floats) -> conflict-free lds.32 frag loads.
// ---------------------------------------------------------------------------
constexpr int TF_LDA   = 36;                 // floats per row (144 B)
constexpr int TF_MAT   = 128 * TF_LDA * 4;   // 18432 B per matrix
constexpr int TF_STG   = 2 * TF_MAT;         // 36864 B per stage (A + B)
constexpr int TF_SMEM  = 2 * TF_STG;         // 73728 B

__device__ __forceinline__ void tf32_gemm_core(
    const float* __restrict__ A, const float* __restrict__ B,
    int K, float acc[4][4][4])
{
    extern __shared__ char smem[];
    const uint32_t sb = smem_u32(smem);

    const int tid = threadIdx.x;
    const int wid = tid >> 5;
    const int lid = tid & 31;
    const int bm  = blockIdx.y * 128;
    const int bn  = blockIdx.x * 128;
    const int wm  = wid >> 2;          // 0..1
    const int wn  = wid & 3;           // 0..3
    const int lg  = lid >> 2;          // group 0..7
    const int lt  = lid & 3;           // thread-in-group

    const int nIter = K / 32;

    auto load_chunk = [&](int c, int s) {
        const int koff = c * 32;
        const uint32_t st = sb + (uint32_t)s * TF_STG;
        #pragma unroll
        for (int i = tid; i < 2048; i += 256) {
            const int mat = i >> 10;                  // 0=A, 1=B
            const int r   = (i >> 3) & 127;
            const int q   = i & 7;                    // 4-float segment
            const uint32_t d = (uint32_t)(mat * TF_MAT + r * 144 + q * 16);
            const float* gp = (mat ? B + (size_t)(bn + r) * K
                                   : A + (size_t)(bm + r) * K) + koff + q * 4;
            cp_async16(st + d, gp);
        }
        cp_commit();
    };

    load_chunk(0, 0);
    load_chunk(1, 1);

    for (int c = 0; c < nIter; c++) {
        if (c + 2 < nIter) cp_wait1(); else cp_wait0();
        __syncthreads();

        const uint32_t st = sb + (uint32_t)(c & 1) * TF_STG;
        const uint32_t sA = st;
        const uint32_t sB = st + TF_MAT;

        #pragma unroll
        for (int k8 = 0; k8 < 32; k8 += 8) {
            uint32_t af[4][4], bf[4][2];
            #pragma unroll
            for (int mt = 0; mt < 4; mt++) {
                const uint32_t base = sA + (uint32_t)((wm * 64 + mt * 16 + lg) * 144
                                                      + (k8 + lt) * 4);
                af[mt][0] = lds32(base);
                af[mt][1] = lds32(base + 8 * 144);
                af[mt][2] = lds32(base + 16);
                af[mt][3] = lds32(base + 8 * 144 + 16);
            }
            #pragma unroll
            for (int nt = 0; nt < 4; nt++) {
                const uint32_t base = sB + (uint32_t)((wn * 32 + nt * 8 + lg) * 144
                                                      + (k8 + lt) * 4);
                bf[nt][0] = lds32(base);
                bf[nt][1] = lds32(base + 16);
            }
            #pragma unroll
            for (int mt = 0; mt < 4; mt++)
                #pragma unroll
                for (int nt = 0; nt < 4; nt++)
                    mma16808(acc[mt][nt], af[mt], bf[nt]);
        }
        __syncthreads();
        if (c + 2 < nIter) load_chunk(c + 2, c & 1);
    }
}

// Out-projection: tf32 GEMM, plain fp32 store to d_out
__global__ void __launch_bounds__(256)
tf_gemm(const float* __restrict__ A, const float* __restrict__ B,
        float* __restrict__ C, int N, int K)
{
    float acc[4][4][4] = {};
    tf32_gemm_core(A, B, K, acc);

    const int tid = threadIdx.x;
    const int wid = tid >> 5;
    const int lid = tid & 31;
    const int bm  = blockIdx.y * 128;
    const int bn  = blockIdx.x * 128;
    const int wm  = wid >> 2;
    const int wn  = wid & 3;
    const int cr  = lid >> 2;
    const int cc  = (lid & 3) * 2;
    #pragma unroll
    for (int mt = 0; mt < 4; mt++) {
        #pragma unroll
        for (int nt = 0; nt < 4; nt++) {
            const int row = bm + wm * 64 + mt * 16 + cr;
            const int col = bn + wn * 32 + nt * 8 + cc;
            float2 v0 = {acc[mt][nt][0], acc[mt][nt][1]};
            float2 v1 = {acc[mt][nt][2], acc[mt][nt][3]};
            *(float2*)&C[(size_t)row * N + col]       = v0;
            *(float2*)&C[(size_t)(row + 8) * N + col] = v1;
        }
    }
}

// Fused QKV projection (tf32): z=0 Q (rope+scale+split), z=1 K (rope+split), z=2 V (split)
__global__ void __launch_bounds__(256)
tf_gemm_qkv(const float* __restrict__ xt, const float* __restrict__ wt,
            __nv_bfloat16* __restrict__ qhi, __nv_bfloat16* __restrict__ qlo,
            __nv_bfloat16* __restrict__ khi, __nv_bfloat16* __restrict__ klo,
            __nv_bfloat16* __restrict__ vhi, __nv_bfloat16* __restrict__ vlo)
{
    const int z = blockIdx.z;
    const float* B = wt + (size_t)z * Dd * Dd;

    float acc[4][4][4] = {};
    tf32_gemm_core(xt, B, Dd, acc);

    __nv_bfloat16* dhi = (z == 0) ? qhi : (z == 1) ? khi : vhi;
    __nv_bfloat16* dlo = (z == 0) ? qlo : (z == 1) ? klo : vlo;
    const float scale = (z == 0) ? 0.18033688011112042f : 1.0f;  // 0.125*log2(e)

    const int tid = threadIdx.x;
    const int wid = tid >> 5;
    const int lid = tid & 31;
    const int bm  = blockIdx.y * 128;
    const int bn  = blockIdx.x * 128;
    const int wm  = wid >> 2;
    const int wn  = wid & 3;
    const int cr  = lid >> 2;
    const int cc  = (lid & 3) * 2;

    #pragma unroll
    for (int mt = 0; mt < 4; mt++) {
        #pragma unroll
        for (int nt = 0; nt < 4; nt++) {
            const int row0 = bm + wm * 64 + mt * 16 + cr;
            const int col  = bn + wn * 32 + nt * 8 + cc;   // even -> rope pair
            float a0 = acc[mt][nt][0], a1 = acc[mt][nt][1];
            float b0 = acc[mt][nt][2], b1 = acc[mt][nt][3];
            if (z < 2) {
                const int j = (col & 63) >> 1;
                const float2 cs0 = g_csn[(row0 & (Ss - 1)) * 32 + j];
                const float2 cs1 = g_csn[((row0 + 8) & (Ss - 1)) * 32 + j];
                float t0 = cs0.x * a0 - cs0.y * a1;
                float t1 = cs0.y * a0 + cs0.x * a1;
                a0 = t0 * scale; a1 = t1 * scale;
                t0 = cs1.x * b0 - cs1.y * b1;
                t1 = cs1.y * b0 + cs1.x * b1;
                b0 = t0 * scale; b1 = t1 * scale;
            }
            {
                const uint32_t hb = pack_bf16(a0, a1);
                const uint32_t lb = pack_bf16(a0 - __uint_as_float(hb << 16),
                                              a1 - __uint_as_float(hb & 0xFFFF0000u));
                const size_t idx = (size_t)row0 * Dd + col;
                *(uint32_t*)&dhi[idx] = hb;
                *(uint32_t*)&dlo[idx] = lb;
            }
            {
                const uint32_t hb = pack_bf16(b0, b1);
                const uint32_t lb = pack_bf16(b0 - __uint_as_float(hb << 16),
                                              b1 - __uint_as_float(hb & 0xFFFF0000u));
                const size_t idx = (size_t)(row0 + 8) * Dd + col;
                *(uint32_t*)&dhi[idx] = hb;
                *(uint32_t*)&dlo[idx] = lb;
            }
        }
    }
}

// ---------------------------------------------------------------------------
// Prep kernels: round fp32 -> tf32 (rna). Unbiased, error ~2^-12.
// ---------------------------------------------------------------------------
__global__ void prep_x(const float* __restrict__ src, float* __restrict__ dst, int n4)
{
    int i = blockIdx.x * blockDim.x + threadIdx.x;
    if (i >= n4) return;
    float4 x = ((const float4*)src)[i];
    float4 y = { to_tf32(x.x), to_tf32(x.y), to_tf32(x.z), to_tf32(x.w) };
    ((float4*)dst)[i] = y;
}

__global__ void prep_w4(const float* __restrict__ w0, const float* __restrict__ w1,
                        const float* __restrict__ w2, const float* __restrict__ w3,
                        float* __restrict__ dst)
{
    const int z = blockIdx.z;
    const float* src = (z == 0) ? w0 : (z == 1) ? w1 : (z == 2) ? w2 : w3;
    const int n4 = Dd * Dd / 4;
    int i = blockIdx.x * blockDim.x + threadIdx.x;
    if (i >= n4) return;
    float4 x = ((const float4*)src)[i];
    float4 y = { to_tf32(x.x), to_tf32(x.y), to_tf32(x.z), to_tf32(x.w) };
    ((float4*)(dst + (size_t)z * Dd * Dd))[i] = y;
}

// RoPE cos/sin table from token positions
__global__ void rope_cs(const int* __restrict__ pos)
{
    int idx = blockIdx.x * blockDim.x + threadIdx.x;
    if (idx >= Ss * 32) return;
    const int s = idx >> 5;
    const int j = idx & 31;
    const float p    = (float)pos[s];
    const float freq = exp2f((float)j * (-2.0f / 64.0f) * 13.28771237954945f);
    float sn, cs;
    sincosf(p * freq, &sn, &cs);
    g_csn[idx] = make_float2(cs, sn);
}

// ---------------------------------------------------------------------------
// Tensor-core causal flash attention (R8/R13 winner; epilogue now writes
// tf32-rounded fp32 for the tf32 out-projection).
// ---------------------------------------------------------------------------
constexpr int FA_LD   = 72;
constexpr int FA_MATB = 64 * FA_LD * 2;
constexpr int FA_STG  = 4 * FA_MATB;
constexpr int FA_SMEM = 2 * FA_STG;

__global__ void __launch_bounds__(256)
fa_mma(const __nv_bfloat16* __restrict__ qhi, const __nv_bfloat16* __restrict__ qlo,
       const __nv_bfloat16* __restrict__ khi, const __nv_bfloat16* __restrict__ klo,
       const __nv_bfloat16* __restrict__ vhi, const __nv_bfloat16* __restrict__ vlo,
       float* __restrict__ of)
{
    extern __shared__ char smem[];
    const uint32_t sb = smem_u32(smem);

    const int tid = threadIdx.x;
    const int wid = tid >> 5;
    const int lid = tid & 31;
    const int bh  = blockIdx.y;
    const int b   = bh >> 4;
    const int h   = bh & (Hh - 1);
    const int q0  = blockIdx.x * 128;
    const size_t gbase = (size_t)(b * Ss) * Dd + h * DKk;

    const int ri = lid & 7;
    const int g  = lid >> 3;
    const int ag_r = ((g & 1) << 3) + ri;
    const int ag_c = (g >> 1) << 3;
    const int bg_r = ((g >> 1) << 3) + ri;
    const int bg_c = (g & 1) << 3;
    const int tr_r = lid & 15;
    const int tr_c = (lid >> 4) << 3;

    #pragma unroll
    for (int i = tid; i < 2048; i += 256) {
        const int mat = i >> 10;
        const int r   = (i >> 3) & 127;
        const int c8  = (i & 7) * 8;
        const __nv_bfloat16* src = (mat ? qlo : qhi) + gbase + (size_t)(q0 + r) * Dd + c8;
        cp_async16(sb + (uint32_t)mat * (128 * 144) + r * 144 + c8 * 2, src);
    }
    cp_commit();
    cp_wait0();
    __syncthreads();

    uint32_t qh[4][4], ql[4][4];
    #pragma unroll
    for (int kt = 0; kt < 4; kt++) {
        const uint32_t off = (uint32_t)((wid * 16 + ag_r) * 144 + (kt * 16 + ag_c) * 2);
        ldsm4(qh[kt], sb + off);
        ldsm4(ql[kt], sb + 128 * 144 + off);
    }
    __syncthreads();

    float o[8][4] = {};
    float m0 = -1e30f, m1 = -1e30f, l0 = 0.f, l1 = 0.f;

    const int ntile = q0 / 64 + 2;

    auto loadKV = [&](int t, int s) {
        const int k0 = t * 64;
        const uint32_t st = sb + (uint32_t)s * FA_STG;
        #pragma unroll
        for (int i = tid; i < 2048; i += 256) {
            const int mat = i >> 9;
            const int r   = (i >> 3) & 63;
            const int c8  = (i & 7) * 8;
            const __nv_bfloat16* gp =
                (mat == 0 ? khi : mat == 1 ? klo : mat == 2 ? vhi : vlo)
                + gbase + (size_t)(k0 + r) * Dd + c8;
            cp_async16(st + (uint32_t)mat * FA_MATB + r * 144 + c8 * 2, gp);
        }
        cp_commit();
    };

    loadKV(0, 0);
    loadKV(1, 1);

    for (int t = 0; t < ntile; t++) {
        if (t + 2 < ntile) cp_wait1(); else cp_wait0();
        __syncthreads();

        const int k0 = t * 64;
        const uint32_t st = sb + (uint32_t)(t & 1) * FA_STG;

        if (k0 <= q0 + wid * 16 + 15) {
            float s[8][4] = {};

            #pragma unroll
            for (int kt = 0; kt < 4; kt++) {
                uint32_t kh[4][4], kl[4][4];
                #pragma unroll
                for (int np = 0; np < 4; np++) {
                    const uint32_t off = (uint32_t)((np * 16 + bg_r) * 144
                                                    + (kt * 16 + bg_c) * 2);
                    ldsm4(kh[np], st + off);
                    ldsm4(kl[np], st + FA_MATB + off);
                }
                #pragma unroll
                for (int np = 0; np < 4; np++) {
                    mma16816(s[2 * np],     qh[kt], &kh[np][0]);
                    mma16816(s[2 * np],     qh[kt], &kl[np][0]);
                    mma16816(s[2 * np],     ql[kt], &kh[np][0]);
                    mma16816(s[2 * np + 1], qh[kt], &kh[np][2]);
                    mma16816(s[2 * np + 1], qh[kt], &kl[np][2]);
                    mma16816(s[2 * np + 1], ql[kt], &kh[np][2]);
                }
            }

            if (k0 + 63 > q0 + wid * 16) {
                const int qr0 = q0 + wid * 16 + (lid >> 2);
                #pragma unroll
                for (int nt = 0; nt < 8; nt++) {
                    #pragma unroll
                    for (int j = 0; j < 4; j++) {
                        const int kc = k0 + nt * 8 + (lid & 3) * 2 + (j & 1);
                        const int qr = qr0 + ((j >> 1) << 3);
                        if (kc > qr) s[nt][j] = -1e30f;
                    }
                }
            }

            float mx0 = -1e30f, mx1 = -1e30f;
            #pragma unroll
            for (int nt = 0; nt < 8; nt++) {
                mx0 = fmaxf(mx0, fmaxf(s[nt][0], s[nt][1]));
                mx1 = fmaxf(mx1, fmaxf(s[nt][2], s[nt][3]));
            }
            mx0 = fmaxf(mx0, __shfl_xor_sync(0xFFFFFFFFu, mx0, 1));
            mx0 = fmaxf(mx0, __shfl_xor_sync(0xFFFFFFFFu, mx0, 2));
            mx1 = fmaxf(mx1, __shfl_xor_sync(0xFFFFFFFFu, mx1, 1));
            mx1 = fmaxf(mx1, __shfl_xor_sync(0xFFFFFFFFu, mx1, 2));

            const float mn0 = fmaxf(m0, mx0);
            const float mn1 = fmaxf(m1, mx1);
            const float c0 = ex2(m0 - mn0);
            const float c1 = ex2(m1 - mn1);
            m0 = mn0; m1 = mn1;

            float sum0 = 0.f, sum1 = 0.f;
            #pragma unroll
            for (int nt = 0; nt < 8; nt++) {
                s[nt][0] = ex2(s[nt][0] - mn0);
                s[nt][1] = ex2(s[nt][1] - mn0);
                s[nt][2] = ex2(s[nt][2] - mn1);
                s[nt][3] = ex2(s[nt][3] - mn1);
                sum0 += s[nt][0] + s[nt][1];
                sum1 += s[nt][2] + s[nt][3];
            }
            sum0 += __shfl_xor_sync(0xFFFFFFFFu, sum0, 1);
            sum0 += __shfl_xor_sync(0xFFFFFFFFu, sum0, 2);
            sum1 += __shfl_xor_sync(0xFFFFFFFFu, sum1, 1);
            sum1 += __shfl_xor_sync(0xFFFFFFFFu, sum1, 2);
            l0 = l0 * c0 + sum0;
            l1 = l1 * c1 + sum1;

            #pragma unroll
            for (int nt = 0; nt < 8; nt++) {
                o[nt][0] *= c0; o[nt][1] *= c0;
                o[nt][2] *= c1; o[nt][3] *= c1;
            }

            #pragma unroll
            for (int kt = 0; kt < 4; kt++) {
                uint32_t ph[4], pl[4];
                #pragma unroll
                for (int half = 0; half < 2; half++) {
                    const float* sp = s[2 * kt + half];
                    const uint32_t hA = pack_bf16(sp[0], sp[1]);
                    const uint32_t hB = pack_bf16(sp[2], sp[3]);
                    const float lA0 = sp[0] - __uint_as_float(hA << 16);
                    const float lA1 = sp[1] - __uint_as_float(hA & 0xFFFF0000u);
                    const float lB0 = sp[2] - __uint_as_float(hB << 16);
                    const float lB1 = sp[3] - __uint_as_float(hB & 0xFFFF0000u);
                    ph[2 * half]     = hA;
                    ph[2 * half + 1] = hB;
                    pl[2 * half]     = pack_bf16(lA0, lA1);
                    pl[2 * half + 1] = pack_bf16(lB0, lB1);
                }
                uint32_t pA[4] = {ph[0], ph[1], ph[2], ph[3]};
                uint32_t pB[4] = {pl[0], pl[1], pl[2], pl[3]};

                uint32_t vh[4][4], vl[4][4];
                #pragma unroll
                for (int nn = 0; nn < 4; nn++) {
                    const uint32_t off = (uint32_t)((kt * 16 + tr_r) * 144
                                                    + (nn * 16 + tr_c) * 2);
                    ldsm4t(vh[nn], st + 2 * FA_MATB + off);
                    ldsm4t(vl[nn], st + 3 * FA_MATB + off);
                }
                #pragma unroll
                for (int nn = 0; nn < 4; nn++) {
                    mma16816(o[2 * nn],     pA, &vh[nn][0]);
                    mma16816(o[2 * nn],     pA, &vl[nn][0]);
                    mma16816(o[2 * nn],     pB, &vh[nn][0]);
                    mma16816(o[2 * nn + 1], pA, &vh[nn][2]);
                    mma16816(o[2 * nn + 1], pA, &vl[nn][2]);
                    mma16816(o[2 * nn + 1], pB, &vh[nn][2]);
                }
            }
        }

        __syncthreads();
        if (t + 2 < ntile) loadKV(t + 2, t & 1);
    }

    // epilogue: normalize, round to tf32, store fp32
    const float i0 = 1.f / l0;
    const float i1 = 1.f / l1;
    const int r0 = q0 + wid * 16 + (lid >> 2);
    const int cb = (lid & 3) * 2;
    #pragma unroll
    for (int nt = 0; nt < 8; nt++) {
        const int col = h * DKk + nt * 8 + cb;
        {
            float2 v = { to_tf32(o[nt][0] * i0), to_tf32(o[nt][1] * i0) };
            *(float2*)&of[(size_t)(b * Ss + r0) * Dd + col] = v;
        }
        {
            float2 v = { to_tf32(o[nt][2] * i1), to_tf32(o[nt][3] * i1) };
            *(float2*)&of[(size_t)(b * Ss + r0 + 8) * Dd + col] = v;
        }
    }
}

// ---------------------------------------------------------------------------
// Launch
// ---------------------------------------------------------------------------
extern "C" void kernel_launch(void* const* d_in, const int* in_sizes, int n_in,
                              void* d_out, int out_size)
{
    const float* x   = (const float*)d_in[0];
    const int*   pos = (const int*)  d_in[1];
    const float* WQ  = (const float*)d_in[2];
    const float* WK  = (const float*)d_in[3];
    const float* WV  = (const float*)d_in[4];
    const float* WO  = (const float*)d_in[5];
    float* out = (float*)d_out;

    float *xt, *wt, *of;
    __nv_bfloat16 *qhi, *qlo, *khi, *klo, *vhi, *vlo;
    cudaGetSymbolAddress((void**)&xt, g_xt);
    cudaGetSymbolAddress((void**)&wt, g_wt);
    cudaGetSymbolAddress((void**)&of, g_of);
    cudaGetSymbolAddress((void**)&qhi, g_qhi);
    cudaGetSymbolAddress((void**)&qlo, g_qlo);
    cudaGetSymbolAddress((void**)&khi, g_khi);
    cudaGetSymbolAddress((void**)&klo, g_klo);
    cudaGetSymbolAddress((void**)&vhi, g_vhi);
    cudaGetSymbolAddress((void**)&vlo, g_vlo);

    cudaFuncSetAttribute(tf_gemm,     cudaFuncAttributeMaxDynamicSharedMemorySize, TF_SMEM);
    cudaFuncSetAttribute(tf_gemm_qkv, cudaFuncAttributeMaxDynamicSharedMemorySize, TF_SMEM);
    cudaFuncSetAttribute(fa_mma,      cudaFuncAttributeMaxDynamicSharedMemorySize, FA_SMEM);

    // 1. round x to tf32
    prep_x<<<(MM * Dd / 4 + 255) / 256, 256>>>(x, xt, MM * Dd / 4);
    // 2. round weights to tf32 (one launch, z=4)
    {
        dim3 grid((Dd * Dd / 4 + 255) / 256, 1, 4);
        prep_w4<<<grid, 256>>>(WQ, WK, WV, WO, wt);
    }
    // 3. RoPE cos/sin table
    rope_cs<<<(Ss * 32 + 255) / 256, 256>>>(pos);
    // 4. fused QKV projection (tf32) + RoPE + bf16 split for FA
    {
        dim3 grid(Dd / 128, MM / 128, 3);
        tf_gemm_qkv<<<grid, 256, TF_SMEM>>>(xt, wt, qhi, qlo, khi, klo, vhi, vlo);
    }
    // 5. tensor-core flash attention (bf16 split, unchanged math)
    {
        dim3 fgrid(Ss / 128, Bb * Hh);
        fa_mma<<<fgrid, 256, FA_SMEM>>>(qhi, qlo, khi, klo, vhi, vlo, of);
    }
    // 6. output projection (tf32)
    {
        dim3 grid(Dd / 128, MM / 128);
        tf_gemm<<<grid, 256, TF_SMEM>>>(of, wt + 3 * (size_t)Dd * Dd, out, Dd, Dd);
    }
}